// round 12
// baseline (speedup 1.0000x reference)
#include <cuda_runtime.h>

#define NQ      4       // independent batch quadrants
#define NBQ     32      // CTAs per quadrant (16 dims each)
#define THREADS 512     // 16 warps = rg(4) x kh(4)
#define BB      64
#define SS      2048
#define HH      512
#define VV      25
#define DT      16      // dims per CTA
#define BT      16      // batches per quadrant/CTA
#define ARRV    (NBQ * 16)   // arrivals per quadrant barrier (per-warp)

// per-quadrant h double buffers, dense rows: [q][parity][k*16 + local batch]
__device__ __align__(16) float g_hq[NQ][2][HH * BT];
__device__ unsigned g_cnt[NQ * 32];    // counters 128B apart

__global__ void init_barrier_kernel() {
    for (int q = 0; q < NQ; q++) g_cnt[q * 32] = 0u;
}

__device__ __forceinline__ void ffma2(float2& a, const float2 x, const float2 y) {
    asm("fma.rn.f32x2 %0, %1, %2, %0;"
        : "+l"(reinterpret_cast<unsigned long long&>(a))
        : "l"(reinterpret_cast<const unsigned long long&>(x)),
          "l"(reinterpret_cast<const unsigned long long&>(y)));
}

__device__ __forceinline__ float sigm(float x) {
    float e = __expf(-x);
    return __fdividef(1.f, 1.f + e);
}
__device__ __forceinline__ float tanha(float x) {
    return fmaf(2.f, sigm(2.f * x), -1.f);
}

// per-warp quadrant barrier: syncwarp -> lane0 release-arrive; all lanes acquire-poll
__device__ __forceinline__ void warp_arrive(unsigned* cnt, int lane) {
    __syncwarp();
    if (lane == 0)
        asm volatile("red.release.gpu.global.add.u32 [%0], 1;"
                     :: "l"(cnt) : "memory");
}
__device__ __forceinline__ void warp_poll(unsigned* cnt, unsigned target) {
    unsigned v;
    do {
        asm volatile("ld.acquire.gpu.global.u32 %0, [%1];"
                     : "=r"(v) : "l"(cnt));
    } while (v < target);
}

// smem (floats)
#define WSP_FLOATS  (HH * 68)          // [k][68]: 64 rows (rg*16+gate*4+dj) + 4 pad
#define WXB_FLOATS  (64 * 32)
#define GRD_FLOATS  (16 * 16 * 20)     // [(rg*4+kh)*16 + b][16 rows + 4 pad]
#define SMEM_BYTES  ((WSP_FLOATS + WXB_FLOATS + GRD_FLOATS + 3 * BB) * 4)

__global__ void __launch_bounds__(THREADS, 1) lstm_persistent_kernel(
    const int* __restrict__ tokens, const int* __restrict__ lengths,
    const float* __restrict__ W_ih, const float* __restrict__ W_hh,
    const float* __restrict__ b_ih, const float* __restrict__ b_hh,
    const float* __restrict__ fc_w, const float* __restrict__ fc_b,
    float* __restrict__ out)
{
    extern __shared__ char smem_raw[];
    float* wsp  = reinterpret_cast<float*>(smem_raw);
    float* wxb  = wsp + WSP_FLOATS;
    float* gred = wxb + WXB_FLOATS;
    int*   slen   = reinterpret_cast<int*>(gred + GRD_FLOATS);
    int*   sorder = slen + BB;
    int*   lens   = sorder + BB;

    const int tid = threadIdx.x;
    const int dt = blockIdx.x >> 2, bt = blockIdx.x & 3;   // dim tile, quadrant
    const int d0 = dt * DT, B0 = bt * BT;
    unsigned* cnt = &g_cnt[bt * 32];
    float* hq0 = g_hq[bt][0];
    float* hq1 = g_hq[bt][1];

    // ---- W_hh: wsp[k*68 + rg*16 + gate*4 + dj] ----
    for (int idx = tid; idx < 64 * HH; idx += THREADS) {
        int r = idx >> 9, k = idx & (HH - 1);
        int rg = r >> 4, gate = (r >> 2) & 3, dj = r & 3;
        wsp[k * 68 + r] = W_hh[(gate * HH + d0 + rg * 4 + dj) * HH + k];
    }
    // ---- W_ih + biases ----
    for (int idx = tid; idx < 64 * VV; idx += THREADS) {
        int r = idx / VV, v = idx - r * VV;
        int rg = r >> 4, gate = (r >> 2) & 3, dj = r & 3;
        int R = gate * HH + d0 + rg * 4 + dj;
        wxb[r * 32 + v] = W_ih[R * VV + v] + b_ih[R] + b_hh[R];
    }
    // ---- stable descending argsort ----
    if (tid < BB) lens[tid] = lengths[tid];
    __syncthreads();
    if (tid < BB) {
        int L = lens[tid], rk = 0;
        for (int b2 = 0; b2 < BB; b2++) {
            int L2 = lens[b2];
            rk += (L2 > L) || (L2 == L && b2 < tid);
        }
        sorder[rk] = tid;
        slen[rk]   = L;
    }
    // ---- zero this CTA's cells in quadrant h buffer 0 ----
    if (tid < DT * BT) {
        hq0[(d0 + (tid >> 4)) * BT + (tid & 15)] = 0.f;
    }
    __syncthreads();   // block HB: smem init + zeros visible to all warps pre-arrive
    const int ctalen = slen[B0];          // quadrant length (max of its 16, sorted)

    // warp setup
    const int w = tid >> 5, lane = tid & 31;
    const int rg = w >> 2, kh = w & 3;
    const int kq = lane >> 2, bp = lane & 3;
    const int b2 = (lane >> 2) & 1, b3 = (lane >> 3) & 1, b4 = (lane >> 4) & 1;
    const int kbase = kh * 128 + kq;

    // activation warps: kh==rg -> cell dj=adj; kh==rg^2 -> cell dj=adj+2
    const bool actw = (kh == rg) || (kh == (rg ^ 2));
    const int cellsel = (kh == (rg ^ 2)) ? 1 : 0;
    const int ab = lane & 15, adj = lane >> 4;
    const int dj = adj + 2 * cellsel;               // in-rg dim 0..3
    const int sb = B0 + ab;
    const int alen = slen[sb];
    const int dG = d0 + rg * 4 + dj;                // this warp-lane's dim
    const int* tokrow = tokens + sorder[sb] * SS;
    float creg = 0.f;

    unsigned target = ARRV;
    warp_arrive(cnt, lane);
    warp_poll(cnt, target);

    for (int t = 0; t < ctalen; t++) {
        const float* hr = (t & 1) ? hq1 : hq0;
        float*       hw = (t & 1) ? hq0 : hq1;

        int tok = 0;
        if (actw && t < alen) tok = __ldg(tokrow + t);

        // ---- matmul: warp = 16 rows x 16 batches x 128 k; dense h rows ----
        const float4* hp = reinterpret_cast<const float4*>(hr) + kbase * 4 + bp;
        const float4* wp = reinterpret_cast<const float4*>(wsp) + kbase * 17 + rg * 4;
        float2 acc[4][2][4];   // [gate][dim-pair][batch]
#pragma unroll
        for (int gg = 0; gg < 4; gg++)
#pragma unroll
            for (int dp2 = 0; dp2 < 2; dp2++)
#pragma unroll
                for (int b = 0; b < 4; b++) acc[gg][dp2][b] = make_float2(0.f, 0.f);

        float4 hbuf[4];
#pragma unroll
        for (int j = 0; j < 4; j++) hbuf[j] = __ldcg(hp + j * 32);   // 8k = 32 f4
#pragma unroll
        for (int blk = 0; blk < 4; blk++) {
            float4 hcur[4];
#pragma unroll
            for (int j = 0; j < 4; j++) hcur[j] = hbuf[j];
            if (blk < 3) {
#pragma unroll
                for (int j = 0; j < 4; j++)
                    hbuf[j] = __ldcg(hp + ((blk + 1) * 4 + j) * 32);
            }
#pragma unroll
            for (int j = 0; j < 4; j++) {
                const float4* wk = wp + (blk * 4 + j) * 136;   // 8 k * 17 f4
                float4 w0 = wk[0], w1 = wk[1], w2 = wk[2], w3 = wk[3];
                float4 h4 = hcur[j];
#pragma unroll
                for (int b = 0; b < 4; b++) {
                    float hv = (b == 0) ? h4.x : (b == 1) ? h4.y
                             : (b == 2) ? h4.z : h4.w;
                    float2 hb = make_float2(hv, hv);
                    ffma2(acc[0][0][b], make_float2(w0.x, w0.y), hb);
                    ffma2(acc[0][1][b], make_float2(w0.z, w0.w), hb);
                    ffma2(acc[1][0][b], make_float2(w1.x, w1.y), hb);
                    ffma2(acc[1][1][b], make_float2(w1.z, w1.w), hb);
                    ffma2(acc[2][0][b], make_float2(w2.x, w2.y), hb);
                    ffma2(acc[2][1][b], make_float2(w2.z, w2.w), hb);
                    ffma2(acc[3][0][b], make_float2(w3.x, w3.y), hb);
                    ffma2(acc[3][1][b], make_float2(w3.z, w3.w), hb);
                }
            }
        }

        // ---- reduce-scatter over kq bits (in-place; 56 shfl/lane) ----
#pragma unroll
        for (int gp = 0; gp < 2; gp++)
#pragma unroll
            for (int dp2 = 0; dp2 < 2; dp2++)
#pragma unroll
                for (int b = 0; b < 4; b++) {
                    float2 X = acc[gp][dp2][b], Y = acc[2 + gp][dp2][b];
                    float gx = b2 ? X.x : Y.x, gy = b2 ? X.y : Y.y;
                    float rx = __shfl_xor_sync(0xffffffffu, gx, 4);
                    float ry = __shfl_xor_sync(0xffffffffu, gy, 4);
                    float kx = b2 ? Y.x : X.x, ky = b2 ? Y.y : X.y;
                    acc[gp][dp2][b] = make_float2(kx + rx, ky + ry);
                }
#pragma unroll
        for (int gp = 0; gp < 2; gp++)
#pragma unroll
            for (int b = 0; b < 4; b++) {
                float2 X = acc[gp][0][b], Y = acc[gp][1][b];
                float gx = b3 ? X.x : Y.x, gy = b3 ? X.y : Y.y;
                float rx = __shfl_xor_sync(0xffffffffu, gx, 8);
                float ry = __shfl_xor_sync(0xffffffffu, gy, 8);
                float kx = b3 ? Y.x : X.x, ky = b3 ? Y.y : X.y;
                acc[gp][0][b] = make_float2(kx + rx, ky + ry);
            }
#pragma unroll
        for (int gp = 0; gp < 2; gp++)
#pragma unroll
            for (int bq = 0; bq < 2; bq++) {
                float2 X = acc[gp][0][bq], Y = acc[gp][0][2 + bq];
                float gx = b4 ? X.x : Y.x, gy = b4 ? X.y : Y.y;
                float rx = __shfl_xor_sync(0xffffffffu, gx, 16);
                float ry = __shfl_xor_sync(0xffffffffu, gy, 16);
                float kx = b4 ? Y.x : X.x, ky = b4 ? Y.y : X.y;
                acc[gp][0][bq] = make_float2(kx + rx, ky + ry);
            }
        // store: gate = 2*b2+gp, dims = 2*b3+{0,1}, batch = 4*bp+2*b4+bq
        // in-row offset = gate*4 + 2*b3 = 8*b2 + 4*gp + 2*b3
        {
            float* gb = gred + ((rg * 4 + kh) * 16) * 20 + (8 * b2 + 2 * b3);
#pragma unroll
            for (int gp = 0; gp < 2; gp++)
#pragma unroll
                for (int bq = 0; bq < 2; bq++) {
                    int batch = 4 * bp + 2 * b4 + bq;
                    *reinterpret_cast<float2*>(
                        gb + batch * 20 + gp * 4) = acc[gp][0][bq];
                }
        }
        // rg-quad sync (4 warps, 128 threads): gred handoff
        asm volatile("bar.sync %0, 128;" :: "r"(rg + 1) : "memory");

        // ---- activation: 2 warps per rg (one per SMSP set), 1 cell/lane ----
        if (actw) {
            if (t < alen) {
                const float* g0 = gred + ((rg * 4 + 0) * 16 + ab) * 20;
                const float* g1 = g0 + 16 * 20;
                const float* g2 = g1 + 16 * 20;
                const float* g3 = g2 + 16 * 20;
                float gi = g0[0 * 4 + dj] + g1[0 * 4 + dj] + g2[0 * 4 + dj] + g3[0 * 4 + dj]
                         + wxb[(rg * 16 + 0 * 4 + dj) * 32 + tok];
                float gf = g0[1 * 4 + dj] + g1[1 * 4 + dj] + g2[1 * 4 + dj] + g3[1 * 4 + dj]
                         + wxb[(rg * 16 + 1 * 4 + dj) * 32 + tok];
                float gg = g0[2 * 4 + dj] + g1[2 * 4 + dj] + g2[2 * 4 + dj] + g3[2 * 4 + dj]
                         + wxb[(rg * 16 + 2 * 4 + dj) * 32 + tok];
                float go = g0[3 * 4 + dj] + g1[3 * 4 + dj] + g2[3 * 4 + dj] + g3[3 * 4 + dj]
                         + wxb[(rg * 16 + 3 * 4 + dj) * 32 + tok];
                float cn = sigm(gf) * creg + sigm(gi) * tanha(gg);
                creg = cn;
                __stcg(hw + dG * BT + ab, sigm(go) * tanha(cn));
            } else if (t == alen) {
                // first frozen step: mirror final h into the other parity buffer
                __stcg(hw + dG * BT + ab, __ldcg(hr + dG * BT + ab));
            }
        }

        target += ARRV;
        warp_arrive(cnt, lane);
        warp_poll(cnt, target);
    }

    // ---- final FC for this quadrant (dt==0 CTA): warp j -> batch B0+j ----
    if (dt == 0) {
        const float* hf = (ctalen & 1) ? hq1 : hq0;
        int j = tid >> 5, l = tid & 31;
        float p = 0.f;
#pragma unroll
        for (int i = 0; i < 16; i++) {
            int k = l + 32 * i;
            p += __ldcg(hf + k * BT + j) * __ldg(fc_w + k);
        }
#pragma unroll
        for (int m = 16; m >= 1; m >>= 1)
            p += __shfl_xor_sync(0xffffffffu, p, m);
        if (l == 0) out[B0 + j] = p + __ldg(fc_b);
    }
}

extern "C" void kernel_launch(void* const* d_in, const int* in_sizes, int n_in,
                              void* d_out, int out_size) {
    const int*   tokens  = (const int*)d_in[0];
    const int*   lengths = (const int*)d_in[1];
    const float* W_ih    = (const float*)d_in[2];
    const float* W_hh    = (const float*)d_in[3];
    const float* b_ih    = (const float*)d_in[4];
    const float* b_hh    = (const float*)d_in[5];
    const float* fc_w    = (const float*)d_in[6];
    const float* fc_b    = (const float*)d_in[7];
    float* out = (float*)d_out;

    cudaFuncSetAttribute(lstm_persistent_kernel,
                         cudaFuncAttributeMaxDynamicSharedMemorySize, SMEM_BYTES);
    init_barrier_kernel<<<1, 1>>>();
    lstm_persistent_kernel<<<NQ * NBQ, THREADS, SMEM_BYTES>>>(
        tokens, lengths, W_ih, W_hh, b_ih, b_hh, fc_w, fc_b, out);
}

// round 13
// speedup vs baseline: 1.3244x; 1.3244x over previous
#include <cuda_runtime.h>

#define THREADS 512     // 16 warps
#define BB      64
#define SS      2048
#define HH      512
#define VV      25
#define NGC     32      // CTAs per group (barrier population)

// group g owns batches [B0, B0+BT): g0:[0,8) g1:[8,16) g2:[16,32) g3:[32,64)
// dense per-group h double buffer, base = B0*HH floats: [parity][k*BT + b]
__device__ __align__(16) float g_h[2][HH * BB];
__device__ unsigned g_cnt[4 * 32];     // per-group counters, 128B apart

__global__ void init_barrier_kernel() {
    for (int q = 0; q < 4; q++) g_cnt[q * 32] = 0u;
}

__device__ __forceinline__ void ffma2(float2& a, const float2 x, const float2 y) {
    asm("fma.rn.f32x2 %0, %1, %2, %0;"
        : "+l"(reinterpret_cast<unsigned long long&>(a))
        : "l"(reinterpret_cast<const unsigned long long&>(x)),
          "l"(reinterpret_cast<const unsigned long long&>(y)));
}
__device__ __forceinline__ float sigm(float x) {
    float e = __expf(-x);
    return __fdividef(1.f, 1.f + e);
}
__device__ __forceinline__ float tanha(float x) {
    return fmaf(2.f, sigm(2.f * x), -1.f);
}

// group barrier (R11-proven shape): tid0 release-arrive + acquire-poll, pop 32
__device__ __forceinline__ void grp_barrier(int tid, unsigned barno, unsigned* cnt) {
    __syncthreads();
    if (tid == 0) {
        asm volatile("red.release.gpu.global.add.u32 [%0], 1;"
                     :: "l"(cnt) : "memory");
        unsigned v;
        do {
            asm volatile("ld.acquire.gpu.global.u32 %0, [%1];"
                         : "=r"(v) : "l"(cnt));
        } while (v < barno * (unsigned)NGC);
    }
    __syncthreads();
}

// smem (floats)
#define WSP_FLOATS  (HH * 68)      // [k][68]: 64 rows (rg4*16+gate*4+dj) + 4 pad
#define WXB_FLOATS  (64 * 32)
#define GRD_FLOATS  5120           // max over BT variants
#define SMEM_BYTES  ((WSP_FLOATS + WXB_FLOATS + GRD_FLOATS + 3 * BB) * 4)

// ---------------------------------------------------------------------------
template<int BTv>
__device__ __forceinline__ void run_lstm(
    const int* __restrict__ tokens,
    const float* __restrict__ wsp, const float* __restrict__ wxb,
    float* __restrict__ gred, const int* __restrict__ slen,
    const int* __restrict__ sorder,
    float* __restrict__ hq0, float* __restrict__ hq1,
    unsigned* cnt, int B0, int d0, int tid)
{
    const int w = tid >> 5, lane = tid & 31;
    const int ctalen = slen[B0];
    const int b2 = (lane >> 2) & 1, b3 = (lane >> 3) & 1, b4 = (lane >> 4) & 1;
    const int kq = lane >> 2, bp = lane & 3;

    if constexpr (BTv <= 16) {
        // ---- shape: rg(4: 16 rows) x kh(4: 128 k); lane kq8 x bp4 ----
        const int rg = w >> 2, kh = w & 3;
        const int kbase = kh * 128 + kq;
        constexpr int BPL = BTv / 4;           // batches per lane: 2 or 4
        // activation mapping
        const bool actw = (kh == rg);
        const int ab = (BTv == 16) ? (lane & 15) : (lane & 7);
        const int adj = (BTv == 16) ? (lane >> 4) : (lane >> 3);
        const int sb = B0 + ab;
        const int alen = slen[sb];
        const int dG = d0 + rg * 4 + adj;      // BT16: dims dG, dG+2; BT8: dim dG
        const int* tokrow = tokens + sorder[sb] * SS;
        float creg0 = 0.f, creg1 = 0.f;

        unsigned barno = 1;
        for (int t = 0; t < ctalen; t++) {
            const float* hr = (t & 1) ? hq1 : hq0;
            float*       hw = (t & 1) ? hq0 : hq1;
            int tok = 0;
            if (actw && t < alen) tok = __ldg(tokrow + t);

            const float4* wp = reinterpret_cast<const float4*>(wsp)
                               + kbase * 17 + rg * 4;
            float2 acc[4][2][BPL];
#pragma unroll
            for (int gg = 0; gg < 4; gg++)
#pragma unroll
                for (int dp2 = 0; dp2 < 2; dp2++)
#pragma unroll
                    for (int b = 0; b < BPL; b++) acc[gg][dp2][b] = make_float2(0.f, 0.f);

            if constexpr (BTv == 16) {
                const float4* hp = reinterpret_cast<const float4*>(hr) + kbase * 4 + bp;
                float4 hbuf[4];
#pragma unroll
                for (int j = 0; j < 4; j++) hbuf[j] = __ldcg(hp + j * 32);
#pragma unroll
                for (int blk = 0; blk < 4; blk++) {
                    float4 hcur[4];
#pragma unroll
                    for (int j = 0; j < 4; j++) hcur[j] = hbuf[j];
                    if (blk < 3) {
#pragma unroll
                        for (int j = 0; j < 4; j++)
                            hbuf[j] = __ldcg(hp + ((blk + 1) * 4 + j) * 32);
                    }
#pragma unroll
                    for (int j = 0; j < 4; j++) {
                        const float4* wk = wp + (blk * 4 + j) * 136;
                        float4 w0 = wk[0], w1 = wk[1], w2 = wk[2], w3 = wk[3];
                        float4 h4 = hcur[j];
#pragma unroll
                        for (int b = 0; b < 4; b++) {
                            float hv = (b == 0) ? h4.x : (b == 1) ? h4.y
                                     : (b == 2) ? h4.z : h4.w;
                            float2 hb = make_float2(hv, hv);
                            ffma2(acc[0][0][b], make_float2(w0.x, w0.y), hb);
                            ffma2(acc[0][1][b], make_float2(w0.z, w0.w), hb);
                            ffma2(acc[1][0][b], make_float2(w1.x, w1.y), hb);
                            ffma2(acc[1][1][b], make_float2(w1.z, w1.w), hb);
                            ffma2(acc[2][0][b], make_float2(w2.x, w2.y), hb);
                            ffma2(acc[2][1][b], make_float2(w2.z, w2.w), hb);
                            ffma2(acc[3][0][b], make_float2(w3.x, w3.y), hb);
                            ffma2(acc[3][1][b], make_float2(w3.z, w3.w), hb);
                        }
                    }
                }
            } else {   // BTv == 8: h row = 8 floats = 4 float2, lane reads float2
                const float2* hp = reinterpret_cast<const float2*>(hr) + kbase * 4 + bp;
                float2 hbuf[4];
#pragma unroll
                for (int j = 0; j < 4; j++) hbuf[j] = __ldcg(hp + j * 32);
#pragma unroll
                for (int blk = 0; blk < 4; blk++) {
                    float2 hcur[4];
#pragma unroll
                    for (int j = 0; j < 4; j++) hcur[j] = hbuf[j];
                    if (blk < 3) {
#pragma unroll
                        for (int j = 0; j < 4; j++)
                            hbuf[j] = __ldcg(hp + ((blk + 1) * 4 + j) * 32);
                    }
#pragma unroll
                    for (int j = 0; j < 4; j++) {
                        const float4* wk = wp + (blk * 4 + j) * 136;
                        float4 w0 = wk[0], w1 = wk[1], w2 = wk[2], w3 = wk[3];
                        float2 h2 = hcur[j];
#pragma unroll
                        for (int b = 0; b < 2; b++) {
                            float hv = b ? h2.y : h2.x;
                            float2 hb = make_float2(hv, hv);
                            ffma2(acc[0][0][b], make_float2(w0.x, w0.y), hb);
                            ffma2(acc[0][1][b], make_float2(w0.z, w0.w), hb);
                            ffma2(acc[1][0][b], make_float2(w1.x, w1.y), hb);
                            ffma2(acc[1][1][b], make_float2(w1.z, w1.w), hb);
                            ffma2(acc[2][0][b], make_float2(w2.x, w2.y), hb);
                            ffma2(acc[2][1][b], make_float2(w2.z, w2.w), hb);
                            ffma2(acc[3][0][b], make_float2(w3.x, w3.y), hb);
                            ffma2(acc[3][1][b], make_float2(w3.z, w3.w), hb);
                        }
                    }
                }
            }

            // ---- reduce-scatter over kq bits ----
            // R1 (xor4/b2): keep gate pair {2b2, 2b2+1}
#pragma unroll
            for (int gp = 0; gp < 2; gp++)
#pragma unroll
                for (int dp2 = 0; dp2 < 2; dp2++)
#pragma unroll
                    for (int b = 0; b < BPL; b++) {
                        float2 X = acc[gp][dp2][b], Y = acc[2 + gp][dp2][b];
                        float gx = b2 ? X.x : Y.x, gy = b2 ? X.y : Y.y;
                        float rx = __shfl_xor_sync(0xffffffffu, gx, 4);
                        float ry = __shfl_xor_sync(0xffffffffu, gy, 4);
                        float kx = b2 ? Y.x : X.x, ky = b2 ? Y.y : X.y;
                        acc[gp][dp2][b] = make_float2(kx + rx, ky + ry);
                    }
            // R2 (xor8/b3): keep dim-pair b3
#pragma unroll
            for (int gp = 0; gp < 2; gp++)
#pragma unroll
                for (int b = 0; b < BPL; b++) {
                    float2 X = acc[gp][0][b], Y = acc[gp][1][b];
                    float gx = b3 ? X.x : Y.x, gy = b3 ? X.y : Y.y;
                    float rx = __shfl_xor_sync(0xffffffffu, gx, 8);
                    float ry = __shfl_xor_sync(0xffffffffu, gy, 8);
                    float kx = b3 ? Y.x : X.x, ky = b3 ? Y.y : X.y;
                    acc[gp][0][b] = make_float2(kx + rx, ky + ry);
                }
            if constexpr (BTv == 16) {
                // R3 (xor16/b4): keep batch pair {2b4, 2b4+1}
#pragma unroll
                for (int gp = 0; gp < 2; gp++)
#pragma unroll
                    for (int bq = 0; bq < 2; bq++) {
                        float2 X = acc[gp][0][bq], Y = acc[gp][0][2 + bq];
                        float gx = b4 ? X.x : Y.x, gy = b4 ? X.y : Y.y;
                        float rx = __shfl_xor_sync(0xffffffffu, gx, 16);
                        float ry = __shfl_xor_sync(0xffffffffu, gy, 16);
                        float kx = b4 ? Y.x : X.x, ky = b4 ? Y.y : X.y;
                        acc[gp][0][bq] = make_float2(kx + rx, ky + ry);
                    }
                // store: gate 2b2+gp, dims 2b3+{0,1}, batch 4bp+2b4+bq
                float* gb = gred + ((rg * 4 + kh) * 16) * 20 + (8 * b2 + 2 * b3);
#pragma unroll
                for (int gp = 0; gp < 2; gp++)
#pragma unroll
                    for (int bq = 0; bq < 2; bq++) {
                        int batch = 4 * bp + 2 * b4 + bq;
                        *reinterpret_cast<float2*>(gb + batch * 20 + gp * 4)
                            = acc[gp][0][bq];
                    }
            } else {
                // R3 (xor16/b4): keep batch b4 of the lane's pair
                float2 res[2];
#pragma unroll
                for (int gp = 0; gp < 2; gp++) {
                    float2 X = acc[gp][0][0], Y = acc[gp][0][1];
                    float gx = b4 ? X.x : Y.x, gy = b4 ? X.y : Y.y;
                    float rx = __shfl_xor_sync(0xffffffffu, gx, 16);
                    float ry = __shfl_xor_sync(0xffffffffu, gy, 16);
                    float kx = b4 ? Y.x : X.x, ky = b4 ? Y.y : X.y;
                    res[gp] = make_float2(kx + rx, ky + ry);
                }
                // store: gate 2b2+gp, dims 2b3+{0,1}, batch 2bp+b4
                float* gb = gred + ((rg * 4 + kh) * 8 + (2 * bp + b4)) * 20
                            + (8 * b2 + 2 * b3);
#pragma unroll
                for (int gp = 0; gp < 2; gp++)
                    *reinterpret_cast<float2*>(gb + gp * 4) = res[gp];
            }
            asm volatile("bar.sync %0, 128;" :: "r"(rg + 1) : "memory");

            // ---- activation ----
            if (actw) {
                if (t < alen) {
                    constexpr int KST = BTv * 20;        // kh-partial stride
                    const float* g0 = gred + ((rg * 4 + 0) * BTv + ab) * 20;
                    const float* g1 = g0 + KST;
                    const float* g2 = g1 + KST;
                    const float* g3 = g2 + KST;
                    if constexpr (BTv == 16) {
#pragma unroll
                        for (int cell = 0; cell < 2; cell++) {
                            int dj = adj + 2 * cell;
                            float gi = g0[dj] + g1[dj] + g2[dj] + g3[dj]
                                     + wxb[(rg * 16 + dj) * 32 + tok];
                            float gf = g0[4 + dj] + g1[4 + dj] + g2[4 + dj] + g3[4 + dj]
                                     + wxb[(rg * 16 + 4 + dj) * 32 + tok];
                            float gg = g0[8 + dj] + g1[8 + dj] + g2[8 + dj] + g3[8 + dj]
                                     + wxb[(rg * 16 + 8 + dj) * 32 + tok];
                            float go = g0[12 + dj] + g1[12 + dj] + g2[12 + dj] + g3[12 + dj]
                                     + wxb[(rg * 16 + 12 + dj) * 32 + tok];
                            float cold = cell ? creg1 : creg0;
                            float cn = sigm(gf) * cold + sigm(gi) * tanha(gg);
                            if (cell) creg1 = cn; else creg0 = cn;
                            __stcg(hw + (dG + 2 * cell) * 16 + ab,
                                   sigm(go) * tanha(cn));
                        }
                    } else {
                        int dj = adj;   // single cell
                        float gi = g0[dj] + g1[dj] + g2[dj] + g3[dj]
                                 + wxb[(rg * 16 + dj) * 32 + tok];
                        float gf = g0[4 + dj] + g1[4 + dj] + g2[4 + dj] + g3[4 + dj]
                                 + wxb[(rg * 16 + 4 + dj) * 32 + tok];
                        float gg = g0[8 + dj] + g1[8 + dj] + g2[8 + dj] + g3[8 + dj]
                                 + wxb[(rg * 16 + 8 + dj) * 32 + tok];
                        float go = g0[12 + dj] + g1[12 + dj] + g2[12 + dj] + g3[12 + dj]
                                 + wxb[(rg * 16 + 12 + dj) * 32 + tok];
                        float cn = sigm(gf) * creg0 + sigm(gi) * tanha(gg);
                        creg0 = cn;
                        __stcg(hw + dG * 8 + ab, sigm(go) * tanha(cn));
                    }
                } else if (t == alen) {
                    if constexpr (BTv == 16) {
                        __stcg(hw + dG * 16 + ab,       __ldcg(hr + dG * 16 + ab));
                        __stcg(hw + (dG + 2) * 16 + ab, __ldcg(hr + (dG + 2) * 16 + ab));
                    } else {
                        __stcg(hw + dG * 8 + ab, __ldcg(hr + dG * 8 + ab));
                    }
                }
            }
            barno++;
            grp_barrier(tid, barno, cnt);
        }
    } else {
        // ---- BTv == 32: rg(8: 8 rows = 2 dims x 4 gates) x kh(2: 256 k) ----
        const int rg = w >> 1, kh = w & 1;
        const int kbase = kh * 256 + kq;
        const int rg4 = rg >> 1, off = 2 * (rg & 1);   // wsp row group + dim offset
        // activation: every warp, cell (d0 + 2rg + kh, batch lane)
        const int sb = B0 + lane;
        const int alen = slen[sb];
        const int dG = d0 + 2 * rg + kh;
        const int* tokrow = tokens + sorder[sb] * SS;
        float creg = 0.f;

        unsigned barno = 1;
        for (int t = 0; t < ctalen; t++) {
            const float* hr = (t & 1) ? hq1 : hq0;
            float*       hw = (t & 1) ? hq0 : hq1;
            int tok = 0;
            if (t < alen) tok = __ldg(tokrow + t);

            const float4* hp = reinterpret_cast<const float4*>(hr) + kbase * 8 + 2 * bp;
            const float* wbase = wsp + kbase * 68 + rg4 * 16 + off;
            float2 acc[4][8];   // [gate][batch]
#pragma unroll
            for (int gg = 0; gg < 4; gg++)
#pragma unroll
                for (int b = 0; b < 8; b++) acc[gg][b] = make_float2(0.f, 0.f);

            // pipeline: 8 blocks of 4 k-steps; lane k = kbase + 8*(blk*4+j)
            float4 hbuf[8];
#pragma unroll
            for (int j = 0; j < 4; j++) {
                hbuf[2 * j]     = __ldcg(hp + j * 64);
                hbuf[2 * j + 1] = __ldcg(hp + j * 64 + 1);
            }
#pragma unroll 2
            for (int blk = 0; blk < 8; blk++) {
                float4 hcur[8];
#pragma unroll
                for (int j = 0; j < 8; j++) hcur[j] = hbuf[j];
                if (blk < 7) {
#pragma unroll
                    for (int j = 0; j < 4; j++) {
                        hbuf[2 * j]     = __ldcg(hp + ((blk + 1) * 4 + j) * 64);
                        hbuf[2 * j + 1] = __ldcg(hp + ((blk + 1) * 4 + j) * 64 + 1);
                    }
                }
#pragma unroll
                for (int j = 0; j < 4; j++) {
                    const float* wk = wbase + (blk * 4 + j) * 544;   // 8 k * 68
                    float2 wg0 = *reinterpret_cast<const float2*>(wk);
                    float2 wg1 = *reinterpret_cast<const float2*>(wk + 4);
                    float2 wg2 = *reinterpret_cast<const float2*>(wk + 8);
                    float2 wg3 = *reinterpret_cast<const float2*>(wk + 12);
                    float4 hA = hcur[2 * j], hB = hcur[2 * j + 1];
#pragma unroll
                    for (int b = 0; b < 8; b++) {
                        float hv = (b == 0) ? hA.x : (b == 1) ? hA.y
                                 : (b == 2) ? hA.z : (b == 3) ? hA.w
                                 : (b == 4) ? hB.x : (b == 5) ? hB.y
                                 : (b == 6) ? hB.z : hB.w;
                        float2 hb = make_float2(hv, hv);
                        ffma2(acc[0][b], wg0, hb);
                        ffma2(acc[1][b], wg1, hb);
                        ffma2(acc[2][b], wg2, hb);
                        ffma2(acc[3][b], wg3, hb);
                    }
                }
            }

            // reduce-scatter: b2 gate-pair, b3 gate-in-pair, b4 batch-half
#pragma unroll
            for (int gp = 0; gp < 2; gp++)
#pragma unroll
                for (int b = 0; b < 8; b++) {
                    float2 X = acc[gp][b], Y = acc[2 + gp][b];
                    float gx = b2 ? X.x : Y.x, gy = b2 ? X.y : Y.y;
                    float rx = __shfl_xor_sync(0xffffffffu, gx, 4);
                    float ry = __shfl_xor_sync(0xffffffffu, gy, 4);
                    float kx = b2 ? Y.x : X.x, ky = b2 ? Y.y : X.y;
                    acc[gp][b] = make_float2(kx + rx, ky + ry);
                }
#pragma unroll
            for (int b = 0; b < 8; b++) {
                float2 X = acc[0][b], Y = acc[1][b];
                float gx = b3 ? X.x : Y.x, gy = b3 ? X.y : Y.y;
                float rx = __shfl_xor_sync(0xffffffffu, gx, 8);
                float ry = __shfl_xor_sync(0xffffffffu, gy, 8);
                float kx = b3 ? Y.x : X.x, ky = b3 ? Y.y : X.y;
                acc[0][b] = make_float2(kx + rx, ky + ry);
            }
            float2 r4[4];
#pragma unroll
            for (int j = 0; j < 4; j++) {
                float2 X = acc[0][j], Y = acc[0][4 + j];
                float gx = b4 ? X.x : Y.x, gy = b4 ? X.y : Y.y;
                float rx = __shfl_xor_sync(0xffffffffu, gx, 16);
                float ry = __shfl_xor_sync(0xffffffffu, gy, 16);
                float kx = b4 ? Y.x : X.x, ky = b4 ? Y.y : X.y;
                r4[j] = make_float2(kx + rx, ky + ry);
            }
            // store: gate G=2b2+b3, dims {2rg,2rg+1} (f2), batches 8bp+4b4+j
            {
                float* gb = gred + ((rg * 2 + kh) * 32) * 10 + (2 * b2 + b3) * 2;
#pragma unroll
                for (int j = 0; j < 4; j++)
                    *reinterpret_cast<float2*>(gb + (8 * bp + 4 * b4 + j) * 10) = r4[j];
            }
            asm volatile("bar.sync %0, 64;" :: "r"(rg + 1) : "memory");

            // activation: every warp, 1 cell/lane
            if (t < alen) {
                const float* p0 = gred + ((rg * 2 + 0) * 32 + lane) * 10 + kh;
                const float* p1 = gred + ((rg * 2 + 1) * 32 + lane) * 10 + kh;
                int dj = off + kh;
                float gi = p0[0] + p1[0] + wxb[(rg4 * 16 + dj) * 32 + tok];
                float gf = p0[2] + p1[2] + wxb[(rg4 * 16 + 4 + dj) * 32 + tok];
                float gg = p0[4] + p1[4] + wxb[(rg4 * 16 + 8 + dj) * 32 + tok];
                float go = p0[6] + p1[6] + wxb[(rg4 * 16 + 12 + dj) * 32 + tok];
                float cn = sigm(gf) * creg + sigm(gi) * tanha(gg);
                creg = cn;
                __stcg(hw + dG * 32 + lane, sigm(go) * tanha(cn));
            } else if (t == alen) {
                __stcg(hw + dG * 32 + lane, __ldcg(hr + dG * 32 + lane));
            }
            barno++;
            grp_barrier(tid, barno, cnt);
        }
    }
}

// ---------------------------------------------------------------------------
__global__ void __launch_bounds__(THREADS, 1) lstm_persistent_kernel(
    const int* __restrict__ tokens, const int* __restrict__ lengths,
    const float* __restrict__ W_ih, const float* __restrict__ W_hh,
    const float* __restrict__ b_ih, const float* __restrict__ b_hh,
    const float* __restrict__ fc_w, const float* __restrict__ fc_b,
    float* __restrict__ out)
{
    extern __shared__ char smem_raw[];
    float* wsp  = reinterpret_cast<float*>(smem_raw);
    float* wxb  = wsp + WSP_FLOATS;
    float* gred = wxb + WXB_FLOATS;
    int*   slen   = reinterpret_cast<int*>(gred + GRD_FLOATS);
    int*   sorder = slen + BB;
    int*   lens   = sorder + BB;

    const int tid = threadIdx.x;
    const int g  = blockIdx.x >> 5;          // group 0..3
    const int dt = blockIdx.x & 31;          // dim tile 0..31
    const int d0 = dt * 16;
    const int B0g = (g == 0) ? 0 : (g == 1) ? 8 : (g == 2) ? 16 : 32;
    const int BTg = (g <= 1) ? 8 : (g == 2) ? 16 : 32;
    unsigned* cnt = &g_cnt[g * 32];
    float* hq0 = g_h[0] + B0g * HH;
    float* hq1 = g_h[1] + B0g * HH;

    // ---- W_hh: wsp[k*68 + rg4*16 + gate*4 + dj] ----
    for (int idx = tid; idx < 64 * HH; idx += THREADS) {
        int r = idx >> 9, k = idx & (HH - 1);
        int rg4 = r >> 4, gate = (r >> 2) & 3, dj = r & 3;
        wsp[k * 68 + r] = W_hh[(gate * HH + d0 + rg4 * 4 + dj) * HH + k];
    }
    // ---- W_ih + biases ----
    for (int idx = tid; idx < 64 * VV; idx += THREADS) {
        int r = idx / VV, v = idx - r * VV;
        int rg4 = r >> 4, gate = (r >> 2) & 3, dj = r & 3;
        int R = gate * HH + d0 + rg4 * 4 + dj;
        wxb[r * 32 + v] = W_ih[R * VV + v] + b_ih[R] + b_hh[R];
    }
    // ---- stable descending argsort ----
    if (tid < BB) lens[tid] = lengths[tid];
    __syncthreads();
    if (tid < BB) {
        int L = lens[tid], rk = 0;
        for (int b2 = 0; b2 < BB; b2++) {
            int L2 = lens[b2];
            rk += (L2 > L) || (L2 == L && b2 < tid);
        }
        sorder[rk] = tid;
        slen[rk]   = L;
    }
    // ---- zero this CTA's cells in group h buffer 0 ----
    if (tid < 16 * BTg) {
        int d = tid / BTg, b = tid - d * BTg;
        hq0[(d0 + d) * BTg + b] = 0.f;
    }
    __syncthreads();

    grp_barrier(tid, 1u, cnt);

    if (g <= 1)      run_lstm<8>(tokens, wsp, wxb, gred, slen, sorder,
                                 hq0, hq1, cnt, B0g, d0, tid);
    else if (g == 2) run_lstm<16>(tokens, wsp, wxb, gred, slen, sorder,
                                  hq0, hq1, cnt, B0g, d0, tid);
    else             run_lstm<32>(tokens, wsp, wxb, gred, slen, sorder,
                                  hq0, hq1, cnt, B0g, d0, tid);

    // ---- final FC for this group (dt==0 CTA) ----
    if (dt == 0) {
        const int ctalen = slen[B0g];
        const float* hf = ((ctalen & 1) ? g_h[1] : g_h[0]) + B0g * HH;
        int bi = tid >> 4, kp = tid & 15;
        if (bi < BTg) {
            float p = 0.f;
#pragma unroll 8
            for (int i = 0; i < 32; i++) {
                int k = kp * 32 + i;
                p += __ldcg(hf + k * BTg + bi) * __ldg(fc_w + k);
            }
            p += __shfl_xor_sync(0xffffffffu, p, 8);
            p += __shfl_xor_sync(0xffffffffu, p, 4);
            p += __shfl_xor_sync(0xffffffffu, p, 2);
            p += __shfl_xor_sync(0xffffffffu, p, 1);
            if (kp == 0) out[B0g + bi] = p + __ldg(fc_b);
        }
    }
}

extern "C" void kernel_launch(void* const* d_in, const int* in_sizes, int n_in,
                              void* d_out, int out_size) {
    const int*   tokens  = (const int*)d_in[0];
    const int*   lengths = (const int*)d_in[1];
    const float* W_ih    = (const float*)d_in[2];
    const float* W_hh    = (const float*)d_in[3];
    const float* b_ih    = (const float*)d_in[4];
    const float* b_hh    = (const float*)d_in[5];
    const float* fc_w    = (const float*)d_in[6];
    const float* fc_b    = (const float*)d_in[7];
    float* out = (float*)d_out;

    cudaFuncSetAttribute(lstm_persistent_kernel,
                         cudaFuncAttributeMaxDynamicSharedMemorySize, SMEM_BYTES);
    init_barrier_kernel<<<1, 1>>>();
    lstm_persistent_kernel<<<128, THREADS, SMEM_BYTES>>>(
        tokens, lengths, W_ih, W_hh, b_ih, b_hh, fc_w, fc_b, out);
}

// round 14
// speedup vs baseline: 1.3431x; 1.0141x over previous
#include <cuda_runtime.h>

#define THREADS 512     // 16 warps
#define BB      64
#define SS      2048
#define HH      512
#define VV      25
#define NGC     32      // CTAs per group (barrier population)

// group g owns batches [B0, B0+BT): g0:[0,8) g1:[8,16) g2:[16,32) g3:[32,64)
// dense per-group h double buffer, base = B0*HH floats: [parity][k*BT + b]
__device__ __align__(16) float g_h[2][HH * BB];
__device__ unsigned g_cnt[4 * 32];     // per-group counters, 128B apart

__global__ void init_barrier_kernel() {
    for (int q = 0; q < 4; q++) g_cnt[q * 32] = 0u;
}

__device__ __forceinline__ void ffma2(float2& a, const float2 x, const float2 y) {
    asm("fma.rn.f32x2 %0, %1, %2, %0;"
        : "+l"(reinterpret_cast<unsigned long long&>(a))
        : "l"(reinterpret_cast<const unsigned long long&>(x)),
          "l"(reinterpret_cast<const unsigned long long&>(y)));
}
__device__ __forceinline__ float sigm(float x) {
    float e = __expf(-x);
    return __fdividef(1.f, 1.f + e);
}
__device__ __forceinline__ float tanha(float x) {
    return fmaf(2.f, sigm(2.f * x), -1.f);
}

// arrive: full-CTA sync (HB for all warps' stores) then tid0 release-add (32/group)
__device__ __forceinline__ void grp_arrive(int tid, unsigned* cnt) {
    __syncthreads();
    if (tid == 0)
        asm volatile("red.release.gpu.global.add.u32 [%0], 1;"
                     :: "l"(cnt) : "memory");
}
// poll: every warp independently acquire-polls (coalesced same-address loads)
__device__ __forceinline__ void grp_poll(unsigned* cnt, unsigned target) {
    unsigned v;
    do {
        asm volatile("ld.acquire.gpu.global.u32 %0, [%1];"
                     : "=r"(v) : "l"(cnt));
    } while (v < target);
}

// smem (floats)
#define WSP_FLOATS  (HH * 68)      // [k][68]: 64 rows (rg4*16+gate*4+dj) + 4 pad
#define WXB_FLOATS  (64 * 32)
#define GRD_FLOATS  5120           // max over BT variants
#define SMEM_BYTES  ((WSP_FLOATS + WXB_FLOATS + GRD_FLOATS + 3 * BB) * 4)

// ---------------------------------------------------------------------------
template<int BTv>
__device__ __forceinline__ void run_lstm(
    const int* __restrict__ tokens,
    const float* __restrict__ wsp, const float* __restrict__ wxb,
    float* __restrict__ gred, const int* __restrict__ slen,
    const int* __restrict__ sorder,
    float* __restrict__ hq0, float* __restrict__ hq1,
    unsigned* cnt, int B0, int d0, int tid)
{
    const int w = tid >> 5, lane = tid & 31;
    const int ctalen = slen[B0];
    const int b2 = (lane >> 2) & 1, b3 = (lane >> 3) & 1, b4 = (lane >> 4) & 1;
    const int kq = lane >> 2, bp = lane & 3;

    if constexpr (BTv <= 16) {
        // ---- shape: rg(4: 16 rows) x kh(4: 128 k); lane kq8 x bp4 ----
        const int rg = w >> 2, kh = w & 3;
        const int kbase = kh * 128 + kq;
        constexpr int BPL = BTv / 4;           // batches per lane: 2 or 4
        // activation: BT16 -> 2 warps/rg (kh==rg: dims 0,1; kh==rg^2: dims 2,3)
        //             BT8  -> 1 warp/rg (kh==rg), lanes cover 4 dims x 8 batches
        const bool actw = (BTv == 16) ? ((kh == rg) || (kh == (rg ^ 2)))
                                      : (kh == rg);
        const int cellsel = (BTv == 16 && kh == (rg ^ 2)) ? 1 : 0;
        const int ab  = (BTv == 16) ? (lane & 15) : (lane & 7);
        const int adj = (BTv == 16) ? (lane >> 4) : (lane >> 3);
        const int dj  = adj + 2 * cellsel;     // in-rg dim 0..3
        const int sb = B0 + ab;
        const int alen = slen[sb];
        const int dG = d0 + rg * 4 + dj;
        const int* tokrow = tokens + sorder[sb] * SS;
        float creg = 0.f;

        unsigned barno = 1;
        for (int t = 0; t < ctalen; t++) {
            const float* hr = (t & 1) ? hq1 : hq0;
            float*       hw = (t & 1) ? hq0 : hq1;
            int tok = 0;
            if (actw && t < alen) tok = __ldg(tokrow + t);

            const float4* wp = reinterpret_cast<const float4*>(wsp)
                               + kbase * 17 + rg * 4;
            float2 acc[4][2][BPL];
#pragma unroll
            for (int gg = 0; gg < 4; gg++)
#pragma unroll
                for (int dp2 = 0; dp2 < 2; dp2++)
#pragma unroll
                    for (int b = 0; b < BPL; b++) acc[gg][dp2][b] = make_float2(0.f, 0.f);

            if constexpr (BTv == 16) {
                const float4* hp = reinterpret_cast<const float4*>(hr) + kbase * 4 + bp;
                float4 hbuf[4];
#pragma unroll
                for (int j = 0; j < 4; j++) hbuf[j] = __ldcg(hp + j * 32);
#pragma unroll
                for (int blk = 0; blk < 4; blk++) {
                    float4 hcur[4];
#pragma unroll
                    for (int j = 0; j < 4; j++) hcur[j] = hbuf[j];
                    if (blk < 3) {
#pragma unroll
                        for (int j = 0; j < 4; j++)
                            hbuf[j] = __ldcg(hp + ((blk + 1) * 4 + j) * 32);
                    }
#pragma unroll
                    for (int j = 0; j < 4; j++) {
                        const float4* wk = wp + (blk * 4 + j) * 136;
                        float4 w0 = wk[0], w1 = wk[1], w2 = wk[2], w3 = wk[3];
                        float4 h4 = hcur[j];
#pragma unroll
                        for (int b = 0; b < 4; b++) {
                            float hv = (b == 0) ? h4.x : (b == 1) ? h4.y
                                     : (b == 2) ? h4.z : h4.w;
                            float2 hb = make_float2(hv, hv);
                            ffma2(acc[0][0][b], make_float2(w0.x, w0.y), hb);
                            ffma2(acc[0][1][b], make_float2(w0.z, w0.w), hb);
                            ffma2(acc[1][0][b], make_float2(w1.x, w1.y), hb);
                            ffma2(acc[1][1][b], make_float2(w1.z, w1.w), hb);
                            ffma2(acc[2][0][b], make_float2(w2.x, w2.y), hb);
                            ffma2(acc[2][1][b], make_float2(w2.z, w2.w), hb);
                            ffma2(acc[3][0][b], make_float2(w3.x, w3.y), hb);
                            ffma2(acc[3][1][b], make_float2(w3.z, w3.w), hb);
                        }
                    }
                }
            } else {   // BTv == 8: h row = 8 floats, lane reads float2
                const float2* hp = reinterpret_cast<const float2*>(hr) + kbase * 4 + bp;
                float2 hbuf[4];
#pragma unroll
                for (int j = 0; j < 4; j++) hbuf[j] = __ldcg(hp + j * 32);
#pragma unroll
                for (int blk = 0; blk < 4; blk++) {
                    float2 hcur[4];
#pragma unroll
                    for (int j = 0; j < 4; j++) hcur[j] = hbuf[j];
                    if (blk < 3) {
#pragma unroll
                        for (int j = 0; j < 4; j++)
                            hbuf[j] = __ldcg(hp + ((blk + 1) * 4 + j) * 32);
                    }
#pragma unroll
                    for (int j = 0; j < 4; j++) {
                        const float4* wk = wp + (blk * 4 + j) * 136;
                        float4 w0 = wk[0], w1 = wk[1], w2 = wk[2], w3 = wk[3];
                        float2 h2 = hcur[j];
#pragma unroll
                        for (int b = 0; b < 2; b++) {
                            float hv = b ? h2.y : h2.x;
                            float2 hb = make_float2(hv, hv);
                            ffma2(acc[0][0][b], make_float2(w0.x, w0.y), hb);
                            ffma2(acc[0][1][b], make_float2(w0.z, w0.w), hb);
                            ffma2(acc[1][0][b], make_float2(w1.x, w1.y), hb);
                            ffma2(acc[1][1][b], make_float2(w1.z, w1.w), hb);
                            ffma2(acc[2][0][b], make_float2(w2.x, w2.y), hb);
                            ffma2(acc[2][1][b], make_float2(w2.z, w2.w), hb);
                            ffma2(acc[3][0][b], make_float2(w3.x, w3.y), hb);
                            ffma2(acc[3][1][b], make_float2(w3.z, w3.w), hb);
                        }
                    }
                }
            }

            // ---- reduce-scatter over kq bits ----
#pragma unroll
            for (int gp = 0; gp < 2; gp++)
#pragma unroll
                for (int dp2 = 0; dp2 < 2; dp2++)
#pragma unroll
                    for (int b = 0; b < BPL; b++) {
                        float2 X = acc[gp][dp2][b], Y = acc[2 + gp][dp2][b];
                        float gx = b2 ? X.x : Y.x, gy = b2 ? X.y : Y.y;
                        float rx = __shfl_xor_sync(0xffffffffu, gx, 4);
                        float ry = __shfl_xor_sync(0xffffffffu, gy, 4);
                        float kx = b2 ? Y.x : X.x, ky = b2 ? Y.y : X.y;
                        acc[gp][dp2][b] = make_float2(kx + rx, ky + ry);
                    }
#pragma unroll
            for (int gp = 0; gp < 2; gp++)
#pragma unroll
                for (int b = 0; b < BPL; b++) {
                    float2 X = acc[gp][0][b], Y = acc[gp][1][b];
                    float gx = b3 ? X.x : Y.x, gy = b3 ? X.y : Y.y;
                    float rx = __shfl_xor_sync(0xffffffffu, gx, 8);
                    float ry = __shfl_xor_sync(0xffffffffu, gy, 8);
                    float kx = b3 ? Y.x : X.x, ky = b3 ? Y.y : X.y;
                    acc[gp][0][b] = make_float2(kx + rx, ky + ry);
                }
            if constexpr (BTv == 16) {
#pragma unroll
                for (int gp = 0; gp < 2; gp++)
#pragma unroll
                    for (int bq = 0; bq < 2; bq++) {
                        float2 X = acc[gp][0][bq], Y = acc[gp][0][2 + bq];
                        float gx = b4 ? X.x : Y.x, gy = b4 ? X.y : Y.y;
                        float rx = __shfl_xor_sync(0xffffffffu, gx, 16);
                        float ry = __shfl_xor_sync(0xffffffffu, gy, 16);
                        float kx = b4 ? Y.x : X.x, ky = b4 ? Y.y : X.y;
                        acc[gp][0][bq] = make_float2(kx + rx, ky + ry);
                    }
                float* gb = gred + ((rg * 4 + kh) * 16) * 20 + (8 * b2 + 2 * b3);
#pragma unroll
                for (int gp = 0; gp < 2; gp++)
#pragma unroll
                    for (int bq = 0; bq < 2; bq++) {
                        int batch = 4 * bp + 2 * b4 + bq;
                        *reinterpret_cast<float2*>(gb + batch * 20 + gp * 4)
                            = acc[gp][0][bq];
                    }
            } else {
                float2 res[2];
#pragma unroll
                for (int gp = 0; gp < 2; gp++) {
                    float2 X = acc[gp][0][0], Y = acc[gp][0][1];
                    float gx = b4 ? X.x : Y.x, gy = b4 ? X.y : Y.y;
                    float rx = __shfl_xor_sync(0xffffffffu, gx, 16);
                    float ry = __shfl_xor_sync(0xffffffffu, gy, 16);
                    float kx = b4 ? Y.x : X.x, ky = b4 ? Y.y : X.y;
                    res[gp] = make_float2(kx + rx, ky + ry);
                }
                float* gb = gred + ((rg * 4 + kh) * 8 + (2 * bp + b4)) * 20
                            + (8 * b2 + 2 * b3);
#pragma unroll
                for (int gp = 0; gp < 2; gp++)
                    *reinterpret_cast<float2*>(gb + gp * 4) = res[gp];
            }
            asm volatile("bar.sync %0, 128;" :: "r"(rg + 1) : "memory");

            // ---- activation: 1 cell per active lane ----
            if (actw) {
                if (t < alen) {
                    constexpr int KST = BTv * 20;
                    const float* g0 = gred + ((rg * 4 + 0) * BTv + ab) * 20;
                    const float* g1 = g0 + KST;
                    const float* g2 = g1 + KST;
                    const float* g3 = g2 + KST;
                    float gi = g0[dj] + g1[dj] + g2[dj] + g3[dj]
                             + wxb[(rg * 16 + dj) * 32 + tok];
                    float gf = g0[4 + dj] + g1[4 + dj] + g2[4 + dj] + g3[4 + dj]
                             + wxb[(rg * 16 + 4 + dj) * 32 + tok];
                    float gg = g0[8 + dj] + g1[8 + dj] + g2[8 + dj] + g3[8 + dj]
                             + wxb[(rg * 16 + 8 + dj) * 32 + tok];
                    float go = g0[12 + dj] + g1[12 + dj] + g2[12 + dj] + g3[12 + dj]
                             + wxb[(rg * 16 + 12 + dj) * 32 + tok];
                    float cn = sigm(gf) * creg + sigm(gi) * tanha(gg);
                    creg = cn;
                    __stcg(hw + dG * BTv + ab, sigm(go) * tanha(cn));
                } else if (t == alen) {
                    __stcg(hw + dG * BTv + ab, __ldcg(hr + dG * BTv + ab));
                }
            }
            barno++;
            grp_arrive(tid, cnt);
            grp_poll(cnt, barno * (unsigned)NGC);
        }
    } else {
        // ---- BTv == 32: rg(8: 2 dims x 4 gates) x kh(2: 256 k) ----
        const int rg = w >> 1, kh = w & 1;
        const int kbase = kh * 256 + kq;
        const int rg4 = rg >> 1, off = 2 * (rg & 1);
        const int sb = B0 + lane;
        const int alen = slen[sb];
        const int dG = d0 + 2 * rg + kh;
        const int* tokrow = tokens + sorder[sb] * SS;
        float creg = 0.f;

        unsigned barno = 1;
        for (int t = 0; t < ctalen; t++) {
            const float* hr = (t & 1) ? hq1 : hq0;
            float*       hw = (t & 1) ? hq0 : hq1;
            int tok = 0;
            if (t < alen) tok = __ldg(tokrow + t);

            const float4* hp = reinterpret_cast<const float4*>(hr) + kbase * 8 + 2 * bp;
            const float* wbase = wsp + kbase * 68 + rg4 * 16 + off;
            float2 acc[4][8];
#pragma unroll
            for (int gg = 0; gg < 4; gg++)
#pragma unroll
                for (int b = 0; b < 8; b++) acc[gg][b] = make_float2(0.f, 0.f);

            float4 hbuf[8];
#pragma unroll
            for (int j = 0; j < 4; j++) {
                hbuf[2 * j]     = __ldcg(hp + j * 64);
                hbuf[2 * j + 1] = __ldcg(hp + j * 64 + 1);
            }
#pragma unroll 2
            for (int blk = 0; blk < 8; blk++) {
                float4 hcur[8];
#pragma unroll
                for (int j = 0; j < 8; j++) hcur[j] = hbuf[j];
                if (blk < 7) {
#pragma unroll
                    for (int j = 0; j < 4; j++) {
                        hbuf[2 * j]     = __ldcg(hp + ((blk + 1) * 4 + j) * 64);
                        hbuf[2 * j + 1] = __ldcg(hp + ((blk + 1) * 4 + j) * 64 + 1);
                    }
                }
#pragma unroll
                for (int j = 0; j < 4; j++) {
                    const float* wk = wbase + (blk * 4 + j) * 544;
                    float2 wg0 = *reinterpret_cast<const float2*>(wk);
                    float2 wg1 = *reinterpret_cast<const float2*>(wk + 4);
                    float2 wg2 = *reinterpret_cast<const float2*>(wk + 8);
                    float2 wg3 = *reinterpret_cast<const float2*>(wk + 12);
                    float4 hA = hcur[2 * j], hB = hcur[2 * j + 1];
#pragma unroll
                    for (int b = 0; b < 8; b++) {
                        float hv = (b == 0) ? hA.x : (b == 1) ? hA.y
                                 : (b == 2) ? hA.z : (b == 3) ? hA.w
                                 : (b == 4) ? hB.x : (b == 5) ? hB.y
                                 : (b == 6) ? hB.z : hB.w;
                        float2 hb = make_float2(hv, hv);
                        ffma2(acc[0][b], wg0, hb);
                        ffma2(acc[1][b], wg1, hb);
                        ffma2(acc[2][b], wg2, hb);
                        ffma2(acc[3][b], wg3, hb);
                    }
                }
            }

#pragma unroll
            for (int gp = 0; gp < 2; gp++)
#pragma unroll
                for (int b = 0; b < 8; b++) {
                    float2 X = acc[gp][b], Y = acc[2 + gp][b];
                    float gx = b2 ? X.x : Y.x, gy = b2 ? X.y : Y.y;
                    float rx = __shfl_xor_sync(0xffffffffu, gx, 4);
                    float ry = __shfl_xor_sync(0xffffffffu, gy, 4);
                    float kx = b2 ? Y.x : X.x, ky = b2 ? Y.y : X.y;
                    acc[gp][b] = make_float2(kx + rx, ky + ry);
                }
#pragma unroll
            for (int b = 0; b < 8; b++) {
                float2 X = acc[0][b], Y = acc[1][b];
                float gx = b3 ? X.x : Y.x, gy = b3 ? X.y : Y.y;
                float rx = __shfl_xor_sync(0xffffffffu, gx, 8);
                float ry = __shfl_xor_sync(0xffffffffu, gy, 8);
                float kx = b3 ? Y.x : X.x, ky = b3 ? Y.y : X.y;
                acc[0][b] = make_float2(kx + rx, ky + ry);
            }
            float2 r4[4];
#pragma unroll
            for (int j = 0; j < 4; j++) {
                float2 X = acc[0][j], Y = acc[0][4 + j];
                float gx = b4 ? X.x : Y.x, gy = b4 ? X.y : Y.y;
                float rx = __shfl_xor_sync(0xffffffffu, gx, 16);
                float ry = __shfl_xor_sync(0xffffffffu, gy, 16);
                float kx = b4 ? Y.x : X.x, ky = b4 ? Y.y : X.y;
                r4[j] = make_float2(kx + rx, ky + ry);
            }
            {
                float* gb = gred + ((rg * 2 + kh) * 32) * 10 + (2 * b2 + b3) * 2;
#pragma unroll
                for (int j = 0; j < 4; j++)
                    *reinterpret_cast<float2*>(gb + (8 * bp + 4 * b4 + j) * 10) = r4[j];
            }
            asm volatile("bar.sync %0, 64;" :: "r"(rg + 1) : "memory");

            if (t < alen) {
                const float* p0 = gred + ((rg * 2 + 0) * 32 + lane) * 10 + kh;
                const float* p1 = gred + ((rg * 2 + 1) * 32 + lane) * 10 + kh;
                int dj = off + kh;
                float gi = p0[0] + p1[0] + wxb[(rg4 * 16 + dj) * 32 + tok];
                float gf = p0[2] + p1[2] + wxb[(rg4 * 16 + 4 + dj) * 32 + tok];
                float gg = p0[4] + p1[4] + wxb[(rg4 * 16 + 8 + dj) * 32 + tok];
                float go = p0[6] + p1[6] + wxb[(rg4 * 16 + 12 + dj) * 32 + tok];
                float cn = sigm(gf) * creg + sigm(gi) * tanha(gg);
                creg = cn;
                __stcg(hw + dG * 32 + lane, sigm(go) * tanha(cn));
            } else if (t == alen) {
                __stcg(hw + dG * 32 + lane, __ldcg(hr + dG * 32 + lane));
            }
            barno++;
            grp_arrive(tid, cnt);
            grp_poll(cnt, barno * (unsigned)NGC);
        }
    }
}

// ---------------------------------------------------------------------------
__global__ void __launch_bounds__(THREADS, 1) lstm_persistent_kernel(
    const int* __restrict__ tokens, const int* __restrict__ lengths,
    const float* __restrict__ W_ih, const float* __restrict__ W_hh,
    const float* __restrict__ b_ih, const float* __restrict__ b_hh,
    const float* __restrict__ fc_w, const float* __restrict__ fc_b,
    float* __restrict__ out)
{
    extern __shared__ char smem_raw[];
    float* wsp  = reinterpret_cast<float*>(smem_raw);
    float* wxb  = wsp + WSP_FLOATS;
    float* gred = wxb + WXB_FLOATS;
    int*   slen   = reinterpret_cast<int*>(gred + GRD_FLOATS);
    int*   sorder = slen + BB;
    int*   lens   = sorder + BB;

    const int tid = threadIdx.x;
    const int g  = blockIdx.x >> 5;          // group 0..3
    const int dt = blockIdx.x & 31;          // dim tile 0..31
    const int d0 = dt * 16;
    const int B0g = (g == 0) ? 0 : (g == 1) ? 8 : (g == 2) ? 16 : 32;
    const int BTg = (g <= 1) ? 8 : (g == 2) ? 16 : 32;
    unsigned* cnt = &g_cnt[g * 32];
    float* hq0 = g_h[0] + B0g * HH;
    float* hq1 = g_h[1] + B0g * HH;

    // ---- W_hh: wsp[k*68 + rg4*16 + gate*4 + dj] ----
    for (int idx = tid; idx < 64 * HH; idx += THREADS) {
        int r = idx >> 9, k = idx & (HH - 1);
        int rg4 = r >> 4, gate = (r >> 2) & 3, dj = r & 3;
        wsp[k * 68 + r] = W_hh[(gate * HH + d0 + rg4 * 4 + dj) * HH + k];
    }
    // ---- W_ih + biases ----
    for (int idx = tid; idx < 64 * VV; idx += THREADS) {
        int r = idx / VV, v = idx - r * VV;
        int rg4 = r >> 4, gate = (r >> 2) & 3, dj = r & 3;
        int R = gate * HH + d0 + rg4 * 4 + dj;
        wxb[r * 32 + v] = W_ih[R * VV + v] + b_ih[R] + b_hh[R];
    }
    // ---- stable descending argsort ----
    if (tid < BB) lens[tid] = lengths[tid];
    __syncthreads();
    if (tid < BB) {
        int L = lens[tid], rk = 0;
        for (int b2 = 0; b2 < BB; b2++) {
            int L2 = lens[b2];
            rk += (L2 > L) || (L2 == L && b2 < tid);
        }
        sorder[rk] = tid;
        slen[rk]   = L;
    }
    // ---- zero this CTA's cells in group h buffer 0 ----
    if (tid < 16 * BTg) {
        int d = tid / BTg, b = tid - d * BTg;
        hq0[(d0 + d) * BTg + b] = 0.f;
    }

    grp_arrive(tid, cnt);          // includes __syncthreads (init HB)
    grp_poll(cnt, (unsigned)NGC);

    if (g <= 1)      run_lstm<8>(tokens, wsp, wxb, gred, slen, sorder,
                                 hq0, hq1, cnt, B0g, d0, tid);
    else if (g == 2) run_lstm<16>(tokens, wsp, wxb, gred, slen, sorder,
                                  hq0, hq1, cnt, B0g, d0, tid);
    else             run_lstm<32>(tokens, wsp, wxb, gred, slen, sorder,
                                  hq0, hq1, cnt, B0g, d0, tid);

    // ---- final FC for this group (dt==0 CTA) ----
    if (dt == 0) {
        const int ctalen = slen[B0g];
        const float* hf = ((ctalen & 1) ? g_h[1] : g_h[0]) + B0g * HH;
        int bi = tid >> 4, kp = tid & 15;
        if (bi < BTg) {
            float p = 0.f;
#pragma unroll 8
            for (int i = 0; i < 32; i++) {
                int k = kp * 32 + i;
                p += __ldcg(hf + k * BTg + bi) * __ldg(fc_w + k);
            }
            p += __shfl_xor_sync(0xffffffffu, p, 8);
            p += __shfl_xor_sync(0xffffffffu, p, 4);
            p += __shfl_xor_sync(0xffffffffu, p, 2);
            p += __shfl_xor_sync(0xffffffffu, p, 1);
            if (kp == 0) out[B0g + bi] = p + __ldg(fc_b);
        }
    }
}

extern "C" void kernel_launch(void* const* d_in, const int* in_sizes, int n_in,
                              void* d_out, int out_size) {
    const int*   tokens  = (const int*)d_in[0];
    const int*   lengths = (const int*)d_in[1];
    const float* W_ih    = (const float*)d_in[2];
    const float* W_hh    = (const float*)d_in[3];
    const float* b_ih    = (const float*)d_in[4];
    const float* b_hh    = (const float*)d_in[5];
    const float* fc_w    = (const float*)d_in[6];
    const float* fc_b    = (const float*)d_in[7];
    float* out = (float*)d_out;

    cudaFuncSetAttribute(lstm_persistent_kernel,
                         cudaFuncAttributeMaxDynamicSharedMemorySize, SMEM_BYTES);
    init_barrier_kernel<<<1, 1>>>();
    lstm_persistent_kernel<<<128, THREADS, SMEM_BYTES>>>(
        tokens, lengths, W_ih, W_hh, b_ih, b_hh, fc_w, fc_b, out);
}

// round 15
// speedup vs baseline: 1.3501x; 1.0052x over previous
#include <cuda_runtime.h>

#define THREADS 512     // 16 warps
#define BB      64
#define SS      2048
#define HH      512
#define VV      25
#define NGC     32      // CTAs per group (barrier population)

// group g owns batches [B0, B0+BT): g0:[0,8) g1:[8,16) g2:[16,32) g3:[32,64)
__device__ __align__(16) float g_h[2][HH * BB];
__device__ unsigned g_cnt[4 * 32];     // per-group counters, 128B apart

__global__ void init_barrier_kernel() {
    for (int q = 0; q < 4; q++) g_cnt[q * 32] = 0u;
}

__device__ __forceinline__ void ffma2(float2& a, const float2 x, const float2 y) {
    asm("fma.rn.f32x2 %0, %1, %2, %0;"
        : "+l"(reinterpret_cast<unsigned long long&>(a))
        : "l"(reinterpret_cast<const unsigned long long&>(x)),
          "l"(reinterpret_cast<const unsigned long long&>(y)));
}
__device__ __forceinline__ float sigm(float x) {
    float e = __expf(-x);
    return __fdividef(1.f, 1.f + e);
}
__device__ __forceinline__ float tanha(float x) {
    return fmaf(2.f, sigm(2.f * x), -1.f);
}

__device__ __forceinline__ void rel_add(unsigned* cnt) {
    asm volatile("red.release.gpu.global.add.u32 [%0], 1;" :: "l"(cnt) : "memory");
}
__device__ __forceinline__ void acq_poll(unsigned* cnt, unsigned target) {
    unsigned v;
    do {
        asm volatile("ld.acquire.gpu.global.u32 %0, [%1];"
                     : "=r"(v) : "l"(cnt));
    } while (v < target);
}
// R14-style CTA arrive (init + BT32 path)
__device__ __forceinline__ void grp_arrive(int tid, unsigned* cnt) {
    __syncthreads();
    if (tid == 0) rel_add(cnt);
}

// smem (floats)
#define WSP_FLOATS  (HH * 68)      // [k][68]: 64 rows (rg4*16+gate*4+dj) + 4 pad
#define WXB_FLOATS  (64 * 32)
#define GRD_HALF    5120
#define GRD_FLOATS  (2 * GRD_HALF) // double-buffered partials (BT<=16)
#define SMEM_BYTES  ((WSP_FLOATS + WXB_FLOATS + GRD_FLOATS + 3 * BB) * 4)

// ---------------------------------------------------------------------------
template<int BTv>
__device__ __forceinline__ void run_lstm(
    const int* __restrict__ tokens,
    const float* __restrict__ wsp, const float* __restrict__ wxb,
    float* __restrict__ gred, const int* __restrict__ slen,
    const int* __restrict__ sorder,
    float* __restrict__ hq0, float* __restrict__ hq1,
    unsigned* cnt, int B0, int d0, int tid)
{
    const int w = tid >> 5, lane = tid & 31;
    const int ctalen = slen[B0];
    const int b2 = (lane >> 2) & 1, b3 = (lane >> 3) & 1, b4 = (lane >> 4) & 1;
    const int kq = lane >> 2, bp = lane & 3;

    if constexpr (BTv <= 16) {
        // ---- shape: rg(4: 16 rows) x kh(4: 128 k); lane kq8 x bp4 ----
        const int rg = w >> 2, kh = w & 3;
        const int kbase = kh * 128 + kq;
        constexpr int BPL = BTv / 4;
        constexpr int NACT = (BTv == 16) ? 8 : 4;       // act warps per CTA
        const bool actw = (BTv == 16) ? ((kh == rg) || (kh == (rg ^ 2)))
                                      : (kh == rg);
        const int cellsel = (BTv == 16 && kh == (rg ^ 2)) ? 1 : 0;
        const int ab  = (BTv == 16) ? (lane & 15) : (lane & 7);
        const int adj = (BTv == 16) ? (lane >> 4) : (lane >> 3);
        const int dj  = adj + 2 * cellsel;
        const int sb = B0 + ab;
        const int alen = slen[sb];
        const int dG = d0 + rg * 4 + dj;
        const int* tokrow = tokens + sorder[sb] * SS;
        float creg = 0.f;

        for (int t = 0; t < ctalen; t++) {
            // wait for step-t h (init NGC + t act rounds of NGC)
            acq_poll(cnt, (unsigned)(t + 1) * NGC);

            const float* hr = (t & 1) ? hq1 : hq0;
            float*       hw = (t & 1) ? hq0 : hq1;
            float* gredb = gred + (t & 1) * GRD_HALF;
            int tok = 0;
            if (actw && t < alen) tok = __ldg(tokrow + t);

            const float4* wp = reinterpret_cast<const float4*>(wsp)
                               + kbase * 17 + rg * 4;
            float2 acc[4][2][BPL];
#pragma unroll
            for (int gg = 0; gg < 4; gg++)
#pragma unroll
                for (int dp2 = 0; dp2 < 2; dp2++)
#pragma unroll
                    for (int b = 0; b < BPL; b++) acc[gg][dp2][b] = make_float2(0.f, 0.f);

            if constexpr (BTv == 16) {
                const float4* hp = reinterpret_cast<const float4*>(hr) + kbase * 4 + bp;
                float4 hbuf[4];
#pragma unroll
                for (int j = 0; j < 4; j++) hbuf[j] = __ldcg(hp + j * 32);
#pragma unroll
                for (int blk = 0; blk < 4; blk++) {
                    float4 hcur[4];
#pragma unroll
                    for (int j = 0; j < 4; j++) hcur[j] = hbuf[j];
                    if (blk < 3) {
#pragma unroll
                        for (int j = 0; j < 4; j++)
                            hbuf[j] = __ldcg(hp + ((blk + 1) * 4 + j) * 32);
                    }
#pragma unroll
                    for (int j = 0; j < 4; j++) {
                        const float4* wk = wp + (blk * 4 + j) * 136;
                        float4 w0 = wk[0], w1 = wk[1], w2 = wk[2], w3 = wk[3];
                        float4 h4 = hcur[j];
#pragma unroll
                        for (int b = 0; b < 4; b++) {
                            float hv = (b == 0) ? h4.x : (b == 1) ? h4.y
                                     : (b == 2) ? h4.z : h4.w;
                            float2 hb = make_float2(hv, hv);
                            ffma2(acc[0][0][b], make_float2(w0.x, w0.y), hb);
                            ffma2(acc[0][1][b], make_float2(w0.z, w0.w), hb);
                            ffma2(acc[1][0][b], make_float2(w1.x, w1.y), hb);
                            ffma2(acc[1][1][b], make_float2(w1.z, w1.w), hb);
                            ffma2(acc[2][0][b], make_float2(w2.x, w2.y), hb);
                            ffma2(acc[2][1][b], make_float2(w2.z, w2.w), hb);
                            ffma2(acc[3][0][b], make_float2(w3.x, w3.y), hb);
                            ffma2(acc[3][1][b], make_float2(w3.z, w3.w), hb);
                        }
                    }
                }
            } else {
                const float2* hp = reinterpret_cast<const float2*>(hr) + kbase * 4 + bp;
                float2 hbuf[4];
#pragma unroll
                for (int j = 0; j < 4; j++) hbuf[j] = __ldcg(hp + j * 32);
#pragma unroll
                for (int blk = 0; blk < 4; blk++) {
                    float2 hcur[4];
#pragma unroll
                    for (int j = 0; j < 4; j++) hcur[j] = hbuf[j];
                    if (blk < 3) {
#pragma unroll
                        for (int j = 0; j < 4; j++)
                            hbuf[j] = __ldcg(hp + ((blk + 1) * 4 + j) * 32);
                    }
#pragma unroll
                    for (int j = 0; j < 4; j++) {
                        const float4* wk = wp + (blk * 4 + j) * 136;
                        float4 w0 = wk[0], w1 = wk[1], w2 = wk[2], w3 = wk[3];
                        float2 h2 = hcur[j];
#pragma unroll
                        for (int b = 0; b < 2; b++) {
                            float hv = b ? h2.y : h2.x;
                            float2 hb = make_float2(hv, hv);
                            ffma2(acc[0][0][b], make_float2(w0.x, w0.y), hb);
                            ffma2(acc[0][1][b], make_float2(w0.z, w0.w), hb);
                            ffma2(acc[1][0][b], make_float2(w1.x, w1.y), hb);
                            ffma2(acc[1][1][b], make_float2(w1.z, w1.w), hb);
                            ffma2(acc[2][0][b], make_float2(w2.x, w2.y), hb);
                            ffma2(acc[2][1][b], make_float2(w2.z, w2.w), hb);
                            ffma2(acc[3][0][b], make_float2(w3.x, w3.y), hb);
                            ffma2(acc[3][1][b], make_float2(w3.z, w3.w), hb);
                        }
                    }
                }
            }

            // ---- reduce-scatter over kq bits ----
#pragma unroll
            for (int gp = 0; gp < 2; gp++)
#pragma unroll
                for (int dp2 = 0; dp2 < 2; dp2++)
#pragma unroll
                    for (int b = 0; b < BPL; b++) {
                        float2 X = acc[gp][dp2][b], Y = acc[2 + gp][dp2][b];
                        float gx = b2 ? X.x : Y.x, gy = b2 ? X.y : Y.y;
                        float rx = __shfl_xor_sync(0xffffffffu, gx, 4);
                        float ry = __shfl_xor_sync(0xffffffffu, gy, 4);
                        float kx = b2 ? Y.x : X.x, ky = b2 ? Y.y : X.y;
                        acc[gp][dp2][b] = make_float2(kx + rx, ky + ry);
                    }
#pragma unroll
            for (int gp = 0; gp < 2; gp++)
#pragma unroll
                for (int b = 0; b < BPL; b++) {
                    float2 X = acc[gp][0][b], Y = acc[gp][1][b];
                    float gx = b3 ? X.x : Y.x, gy = b3 ? X.y : Y.y;
                    float rx = __shfl_xor_sync(0xffffffffu, gx, 8);
                    float ry = __shfl_xor_sync(0xffffffffu, gy, 8);
                    float kx = b3 ? Y.x : X.x, ky = b3 ? Y.y : X.y;
                    acc[gp][0][b] = make_float2(kx + rx, ky + ry);
                }
            if constexpr (BTv == 16) {
#pragma unroll
                for (int gp = 0; gp < 2; gp++)
#pragma unroll
                    for (int bq = 0; bq < 2; bq++) {
                        float2 X = acc[gp][0][bq], Y = acc[gp][0][2 + bq];
                        float gx = b4 ? X.x : Y.x, gy = b4 ? X.y : Y.y;
                        float rx = __shfl_xor_sync(0xffffffffu, gx, 16);
                        float ry = __shfl_xor_sync(0xffffffffu, gy, 16);
                        float kx = b4 ? Y.x : X.x, ky = b4 ? Y.y : X.y;
                        acc[gp][0][bq] = make_float2(kx + rx, ky + ry);
                    }
                float* gb = gredb + ((rg * 4 + kh) * 16) * 20 + (8 * b2 + 2 * b3);
#pragma unroll
                for (int gp = 0; gp < 2; gp++)
#pragma unroll
                    for (int bq = 0; bq < 2; bq++) {
                        int batch = 4 * bp + 2 * b4 + bq;
                        *reinterpret_cast<float2*>(gb + batch * 20 + gp * 4)
                            = acc[gp][0][bq];
                    }
            } else {
                float2 res[2];
#pragma unroll
                for (int gp = 0; gp < 2; gp++) {
                    float2 X = acc[gp][0][0], Y = acc[gp][0][1];
                    float gx = b4 ? X.x : Y.x, gy = b4 ? X.y : Y.y;
                    float rx = __shfl_xor_sync(0xffffffffu, gx, 16);
                    float ry = __shfl_xor_sync(0xffffffffu, gy, 16);
                    float kx = b4 ? Y.x : X.x, ky = b4 ? Y.y : X.y;
                    res[gp] = make_float2(kx + rx, ky + ry);
                }
                float* gb = gredb + ((rg * 4 + kh) * 8 + (2 * bp + b4)) * 20
                            + (8 * b2 + 2 * b3);
#pragma unroll
                for (int gp = 0; gp < 2; gp++)
                    *reinterpret_cast<float2*>(gb + gp * 4) = res[gp];
            }
            // quad handoff: act warps pass only after quad's gred (and h reads) done
            asm volatile("bar.sync %0, 128;" :: "r"(rg + 1) : "memory");

            // ---- activation: act warps only; then they alone gate the step ----
            if (actw) {
                if (t < alen) {
                    constexpr int KST = BTv * 20;
                    const float* g0 = gredb + ((rg * 4 + 0) * BTv + ab) * 20;
                    const float* g1 = g0 + KST;
                    const float* g2 = g1 + KST;
                    const float* g3 = g2 + KST;
                    float gi = g0[dj] + g1[dj] + g2[dj] + g3[dj]
                             + wxb[(rg * 16 + dj) * 32 + tok];
                    float gf = g0[4 + dj] + g1[4 + dj] + g2[4 + dj] + g3[4 + dj]
                             + wxb[(rg * 16 + 4 + dj) * 32 + tok];
                    float gg = g0[8 + dj] + g1[8 + dj] + g2[8 + dj] + g3[8 + dj]
                             + wxb[(rg * 16 + 8 + dj) * 32 + tok];
                    float go = g0[12 + dj] + g1[12 + dj] + g2[12 + dj] + g3[12 + dj]
                             + wxb[(rg * 16 + 12 + dj) * 32 + tok];
                    float cn = sigm(gf) * creg + sigm(gi) * tanha(gg);
                    creg = cn;
                    __stcg(hw + dG * BTv + ab, sigm(go) * tanha(cn));
                } else if (t == alen) {
                    __stcg(hw + dG * BTv + ab, __ldcg(hr + dG * BTv + ab));
                }
                // act-warp barrier (covers all quads), then single release-add
                asm volatile("bar.sync 5, %0;" :: "n"(NACT * 32) : "memory");
                if (w == 0 && lane == 0) rel_add(cnt);
            }
        }
    } else {
        // ---- BTv == 32 (all warps are act warps): R14 structure ----
        const int rg = w >> 1, kh = w & 1;
        const int kbase = kh * 256 + kq;
        const int rg4 = rg >> 1, off = 2 * (rg & 1);
        const int sb = B0 + lane;
        const int alen = slen[sb];
        const int dG = d0 + 2 * rg + kh;
        const int* tokrow = tokens + sorder[sb] * SS;
        float creg = 0.f;

        for (int t = 0; t < ctalen; t++) {
            acq_poll(cnt, (unsigned)(t + 1) * NGC);
            const float* hr = (t & 1) ? hq1 : hq0;
            float*       hw = (t & 1) ? hq0 : hq1;
            int tok = 0;
            if (t < alen) tok = __ldg(tokrow + t);

            const float4* hp = reinterpret_cast<const float4*>(hr) + kbase * 8 + 2 * bp;
            const float* wbase = wsp + kbase * 68 + rg4 * 16 + off;
            float2 acc[4][8];
#pragma unroll
            for (int gg = 0; gg < 4; gg++)
#pragma unroll
                for (int b = 0; b < 8; b++) acc[gg][b] = make_float2(0.f, 0.f);

            float4 hbuf[8];
#pragma unroll
            for (int j = 0; j < 4; j++) {
                hbuf[2 * j]     = __ldcg(hp + j * 64);
                hbuf[2 * j + 1] = __ldcg(hp + j * 64 + 1);
            }
#pragma unroll 2
            for (int blk = 0; blk < 8; blk++) {
                float4 hcur[8];
#pragma unroll
                for (int j = 0; j < 8; j++) hcur[j] = hbuf[j];
                if (blk < 7) {
#pragma unroll
                    for (int j = 0; j < 4; j++) {
                        hbuf[2 * j]     = __ldcg(hp + ((blk + 1) * 4 + j) * 64);
                        hbuf[2 * j + 1] = __ldcg(hp + ((blk + 1) * 4 + j) * 64 + 1);
                    }
                }
#pragma unroll
                for (int j = 0; j < 4; j++) {
                    const float* wk = wbase + (blk * 4 + j) * 544;
                    float2 wg0 = *reinterpret_cast<const float2*>(wk);
                    float2 wg1 = *reinterpret_cast<const float2*>(wk + 4);
                    float2 wg2 = *reinterpret_cast<const float2*>(wk + 8);
                    float2 wg3 = *reinterpret_cast<const float2*>(wk + 12);
                    float4 hA = hcur[2 * j], hB = hcur[2 * j + 1];
#pragma unroll
                    for (int b = 0; b < 8; b++) {
                        float hv = (b == 0) ? hA.x : (b == 1) ? hA.y
                                 : (b == 2) ? hA.z : (b == 3) ? hA.w
                                 : (b == 4) ? hB.x : (b == 5) ? hB.y
                                 : (b == 6) ? hB.z : hB.w;
                        float2 hb = make_float2(hv, hv);
                        ffma2(acc[0][b], wg0, hb);
                        ffma2(acc[1][b], wg1, hb);
                        ffma2(acc[2][b], wg2, hb);
                        ffma2(acc[3][b], wg3, hb);
                    }
                }
            }

#pragma unroll
            for (int gp = 0; gp < 2; gp++)
#pragma unroll
                for (int b = 0; b < 8; b++) {
                    float2 X = acc[gp][b], Y = acc[2 + gp][b];
                    float gx = b2 ? X.x : Y.x, gy = b2 ? X.y : Y.y;
                    float rx = __shfl_xor_sync(0xffffffffu, gx, 4);
                    float ry = __shfl_xor_sync(0xffffffffu, gy, 4);
                    float kx = b2 ? Y.x : X.x, ky = b2 ? Y.y : X.y;
                    acc[gp][b] = make_float2(kx + rx, ky + ry);
                }
#pragma unroll
            for (int b = 0; b < 8; b++) {
                float2 X = acc[0][b], Y = acc[1][b];
                float gx = b3 ? X.x : Y.x, gy = b3 ? X.y : Y.y;
                float rx = __shfl_xor_sync(0xffffffffu, gx, 8);
                float ry = __shfl_xor_sync(0xffffffffu, gy, 8);
                float kx = b3 ? Y.x : X.x, ky = b3 ? Y.y : X.y;
                acc[0][b] = make_float2(kx + rx, ky + ry);
            }
            float2 r4[4];
#pragma unroll
            for (int j = 0; j < 4; j++) {
                float2 X = acc[0][j], Y = acc[0][4 + j];
                float gx = b4 ? X.x : Y.x, gy = b4 ? X.y : Y.y;
                float rx = __shfl_xor_sync(0xffffffffu, gx, 16);
                float ry = __shfl_xor_sync(0xffffffffu, gy, 16);
                float kx = b4 ? Y.x : X.x, ky = b4 ? Y.y : X.y;
                r4[j] = make_float2(kx + rx, ky + ry);
            }
            {
                float* gb = gred + ((rg * 2 + kh) * 32) * 10 + (2 * b2 + b3) * 2;
#pragma unroll
                for (int j = 0; j < 4; j++)
                    *reinterpret_cast<float2*>(gb + (8 * bp + 4 * b4 + j) * 10) = r4[j];
            }
            asm volatile("bar.sync %0, 64;" :: "r"(rg + 1) : "memory");

            if (t < alen) {
                const float* p0 = gred + ((rg * 2 + 0) * 32 + lane) * 10 + kh;
                const float* p1 = gred + ((rg * 2 + 1) * 32 + lane) * 10 + kh;
                int dj = off + kh;
                float gi = p0[0] + p1[0] + wxb[(rg4 * 16 + dj) * 32 + tok];
                float gf = p0[2] + p1[2] + wxb[(rg4 * 16 + 4 + dj) * 32 + tok];
                float gg = p0[4] + p1[4] + wxb[(rg4 * 16 + 8 + dj) * 32 + tok];
                float go = p0[6] + p1[6] + wxb[(rg4 * 16 + 12 + dj) * 32 + tok];
                float cn = sigm(gf) * creg + sigm(gi) * tanha(gg);
                creg = cn;
                __stcg(hw + dG * 32 + lane, sigm(go) * tanha(cn));
            } else if (t == alen) {
                __stcg(hw + dG * 32 + lane, __ldcg(hr + dG * 32 + lane));
            }
            grp_arrive(tid, cnt);
        }
    }
}

// ---------------------------------------------------------------------------
__global__ void __launch_bounds__(THREADS, 1) lstm_persistent_kernel(
    const int* __restrict__ tokens, const int* __restrict__ lengths,
    const float* __restrict__ W_ih, const float* __restrict__ W_hh,
    const float* __restrict__ b_ih, const float* __restrict__ b_hh,
    const float* __restrict__ fc_w, const float* __restrict__ fc_b,
    float* __restrict__ out)
{
    extern __shared__ char smem_raw[];
    float* wsp  = reinterpret_cast<float*>(smem_raw);
    float* wxb  = wsp + WSP_FLOATS;
    float* gred = wxb + WXB_FLOATS;
    int*   slen   = reinterpret_cast<int*>(gred + GRD_FLOATS);
    int*   sorder = slen + BB;
    int*   lens   = sorder + BB;

    const int tid = threadIdx.x;
    const int g  = blockIdx.x >> 5;          // group 0..3
    const int dt = blockIdx.x & 31;          // dim tile 0..31
    const int d0 = dt * 16;
    const int B0g = (g == 0) ? 0 : (g == 1) ? 8 : (g == 2) ? 16 : 32;
    const int BTg = (g <= 1) ? 8 : (g == 2) ? 16 : 32;
    unsigned* cnt = &g_cnt[g * 32];
    float* hq0 = g_h[0] + B0g * HH;
    float* hq1 = g_h[1] + B0g * HH;

    for (int idx = tid; idx < 64 * HH; idx += THREADS) {
        int r = idx >> 9, k = idx & (HH - 1);
        int rg4 = r >> 4, gate = (r >> 2) & 3, dj = r & 3;
        wsp[k * 68 + r] = W_hh[(gate * HH + d0 + rg4 * 4 + dj) * HH + k];
    }
    for (int idx = tid; idx < 64 * VV; idx += THREADS) {
        int r = idx / VV, v = idx - r * VV;
        int rg4 = r >> 4, gate = (r >> 2) & 3, dj = r & 3;
        int R = gate * HH + d0 + rg4 * 4 + dj;
        wxb[r * 32 + v] = W_ih[R * VV + v] + b_ih[R] + b_hh[R];
    }
    if (tid < BB) lens[tid] = lengths[tid];
    __syncthreads();
    if (tid < BB) {
        int L = lens[tid], rk = 0;
        for (int b2 = 0; b2 < BB; b2++) {
            int L2 = lens[b2];
            rk += (L2 > L) || (L2 == L && b2 < tid);
        }
        sorder[rk] = tid;
        slen[rk]   = L;
    }
    if (tid < 16 * BTg) {
        int d = tid / BTg, b = tid - d * BTg;
        hq0[(d0 + d) * BTg + b] = 0.f;
    }

    grp_arrive(tid, cnt);          // init: __syncthreads + tid0 release

    if (g <= 1)      run_lstm<8>(tokens, wsp, wxb, gred, slen, sorder,
                                 hq0, hq1, cnt, B0g, d0, tid);
    else if (g == 2) run_lstm<16>(tokens, wsp, wxb, gred, slen, sorder,
                                  hq0, hq1, cnt, B0g, d0, tid);
    else             run_lstm<32>(tokens, wsp, wxb, gred, slen, sorder,
                                  hq0, hq1, cnt, B0g, d0, tid);

    // ---- final FC for this group (dt==0 CTA) ----
    if (dt == 0) {
        const int ctalen = slen[B0g];
        acq_poll(cnt, (unsigned)(ctalen + 1) * NGC);   // final h visible
        const float* hf = ((ctalen & 1) ? g_h[1] : g_h[0]) + B0g * HH;
        int bi = tid >> 4, kp = tid & 15;
        if (bi < BTg) {
            float p = 0.f;
#pragma unroll 8
            for (int i = 0; i < 32; i++) {
                int k = kp * 32 + i;
                p += __ldcg(hf + k * BTg + bi) * __ldg(fc_w + k);
            }
            p += __shfl_xor_sync(0xffffffffu, p, 8);
            p += __shfl_xor_sync(0xffffffffu, p, 4);
            p += __shfl_xor_sync(0xffffffffu, p, 2);
            p += __shfl_xor_sync(0xffffffffu, p, 1);
            if (kp == 0) out[B0g + bi] = p + __ldg(fc_b);
        }
    }
}

extern "C" void kernel_launch(void* const* d_in, const int* in_sizes, int n_in,
                              void* d_out, int out_size) {
    const int*   tokens  = (const int*)d_in[0];
    const int*   lengths = (const int*)d_in[1];
    const float* W_ih    = (const float*)d_in[2];
    const float* W_hh    = (const float*)d_in[3];
    const float* b_ih    = (const float*)d_in[4];
    const float* b_hh    = (const float*)d_in[5];
    const float* fc_w    = (const float*)d_in[6];
    const float* fc_b    = (const float*)d_in[7];
    float* out = (float*)d_out;

    cudaFuncSetAttribute(lstm_persistent_kernel,
                         cudaFuncAttributeMaxDynamicSharedMemorySize, SMEM_BYTES);
    init_barrier_kernel<<<1, 1>>>();
    lstm_persistent_kernel<<<128, THREADS, SMEM_BYTES>>>(
        tokens, lengths, W_ih, W_hh, b_ih, b_hh, fc_w, fc_b, out);
}

// round 16
// speedup vs baseline: 1.3553x; 1.0038x over previous
#include <cuda_runtime.h>

#define THREADS 512     // 16 warps
#define BB      64
#define SS      2048
#define HH      512
#define VV      25
#define NGC     32      // CTAs per group (barrier population)

// group g owns batches [B0, B0+BT): g0:[0,8) g1:[8,16) g2:[16,32) g3:[32,64)
__device__ __align__(16) float g_h[2][HH * BB];
__device__ unsigned g_cnt[4 * 32];     // per-group counters, 128B apart

__global__ void init_barrier_kernel() {
    for (int q = 0; q < 4; q++) g_cnt[q * 32] = 0u;
}

__device__ __forceinline__ void ffma2(float2& a, const float2 x, const float2 y) {
    asm("fma.rn.f32x2 %0, %1, %2, %0;"
        : "+l"(reinterpret_cast<unsigned long long&>(a))
        : "l"(reinterpret_cast<const unsigned long long&>(x)),
          "l"(reinterpret_cast<const unsigned long long&>(y)));
}
__device__ __forceinline__ float sigm(float x) {
    float e = __expf(-x);
    return __fdividef(1.f, 1.f + e);
}
__device__ __forceinline__ float tanha(float x) {
    return fmaf(2.f, sigm(2.f * x), -1.f);
}

__device__ __forceinline__ void rel_add(unsigned* cnt) {
    asm volatile("red.release.gpu.global.add.u32 [%0], 1;" :: "l"(cnt) : "memory");
}
__device__ __forceinline__ void acq_poll(unsigned* cnt, unsigned target) {
    unsigned v;
    do {
        asm volatile("ld.acquire.gpu.global.u32 %0, [%1];"
                     : "=r"(v) : "l"(cnt));
    } while (v < target);
}
// R14-style CTA arrive (init + BT32 path)
__device__ __forceinline__ void grp_arrive(int tid, unsigned* cnt) {
    __syncthreads();
    if (tid == 0) rel_add(cnt);
}

// smem (floats)
#define WSP_FLOATS  (HH * 68)      // [k][68]: 64 rows (rg4*16+gate*4+dj) + 4 pad
#define WXB_FLOATS  (64 * 32)
#define GRD_HALF    5120
#define GRD_FLOATS  (2 * GRD_HALF) // double-buffered partials (BT<=16)
#define SMEM_BYTES  ((WSP_FLOATS + WXB_FLOATS + GRD_FLOATS + 3 * BB) * 4)

// ---------------------------------------------------------------------------
template<int BTv>
__device__ __forceinline__ void run_lstm(
    const int* __restrict__ tokens,
    const float* __restrict__ wsp, const float* __restrict__ wxb,
    float* __restrict__ gred, const int* __restrict__ slen,
    const int* __restrict__ sorder,
    float* __restrict__ hq0, float* __restrict__ hq1,
    unsigned* cnt, int B0, int d0, int tid)
{
    const int w = tid >> 5, lane = tid & 31;
    const int ctalen = slen[B0];
    const int b2 = (lane >> 2) & 1, b3 = (lane >> 3) & 1, b4 = (lane >> 4) & 1;
    const int kq = lane >> 2, bp = lane & 3;

    if constexpr (BTv <= 16) {
        // ---- shape: rg(4: 16 rows) x kh(4: 128 k); lane kq8 x bp4 ----
        const int rg = w >> 2, kh = w & 3;
        const int kbase = kh * 128 + kq;
        constexpr int BPL = BTv / 4;
        constexpr int NACT = (BTv == 16) ? 8 : 4;       // act warps per CTA
        const bool actw = (BTv == 16) ? ((kh == rg) || (kh == (rg ^ 2)))
                                      : (kh == rg);
        const int cellsel = (BTv == 16 && kh == (rg ^ 2)) ? 1 : 0;
        const int ab  = (BTv == 16) ? (lane & 15) : (lane & 7);
        const int adj = (BTv == 16) ? (lane >> 4) : (lane >> 3);
        const int dj  = adj + 2 * cellsel;
        const int sb = B0 + ab;
        const int alen = slen[sb];
        const int dG = d0 + rg * 4 + dj;
        const int* tokrow = tokens + sorder[sb] * SS;
        float creg = 0.f;

        for (int t = 0; t < ctalen; t++) {
            // wait for step-t h (init NGC + t act rounds of NGC)
            acq_poll(cnt, (unsigned)(t + 1) * NGC);

            const float* hr = (t & 1) ? hq1 : hq0;
            float*       hw = (t & 1) ? hq0 : hq1;
            float* gredb = gred + (t & 1) * GRD_HALF;
            int tok = 0;
            if (actw && t < alen) tok = __ldg(tokrow + t);

            const float4* wp = reinterpret_cast<const float4*>(wsp)
                               + kbase * 17 + rg * 4;
            float2 acc[4][2][BPL];
#pragma unroll
            for (int gg = 0; gg < 4; gg++)
#pragma unroll
                for (int dp2 = 0; dp2 < 2; dp2++)
#pragma unroll
                    for (int b = 0; b < BPL; b++) acc[gg][dp2][b] = make_float2(0.f, 0.f);

            if constexpr (BTv == 16) {
                const float4* hp = reinterpret_cast<const float4*>(hr) + kbase * 4 + bp;
                float4 hbuf[4];
#pragma unroll
                for (int j = 0; j < 4; j++) hbuf[j] = __ldcg(hp + j * 32);
#pragma unroll
                for (int blk = 0; blk < 4; blk++) {
                    float4 hcur[4];
#pragma unroll
                    for (int j = 0; j < 4; j++) hcur[j] = hbuf[j];
                    if (blk < 3) {
#pragma unroll
                        for (int j = 0; j < 4; j++)
                            hbuf[j] = __ldcg(hp + ((blk + 1) * 4 + j) * 32);
                    }
#pragma unroll
                    for (int j = 0; j < 4; j++) {
                        const float4* wk = wp + (blk * 4 + j) * 136;
                        float4 w0 = wk[0], w1 = wk[1], w2 = wk[2], w3 = wk[3];
                        float4 h4 = hcur[j];
#pragma unroll
                        for (int b = 0; b < 4; b++) {
                            float hv = (b == 0) ? h4.x : (b == 1) ? h4.y
                                     : (b == 2) ? h4.z : h4.w;
                            float2 hb = make_float2(hv, hv);
                            ffma2(acc[0][0][b], make_float2(w0.x, w0.y), hb);
                            ffma2(acc[0][1][b], make_float2(w0.z, w0.w), hb);
                            ffma2(acc[1][0][b], make_float2(w1.x, w1.y), hb);
                            ffma2(acc[1][1][b], make_float2(w1.z, w1.w), hb);
                            ffma2(acc[2][0][b], make_float2(w2.x, w2.y), hb);
                            ffma2(acc[2][1][b], make_float2(w2.z, w2.w), hb);
                            ffma2(acc[3][0][b], make_float2(w3.x, w3.y), hb);
                            ffma2(acc[3][1][b], make_float2(w3.z, w3.w), hb);
                        }
                    }
                }
            } else {
                const float2* hp = reinterpret_cast<const float2*>(hr) + kbase * 4 + bp;
                float2 hbuf[4];
#pragma unroll
                for (int j = 0; j < 4; j++) hbuf[j] = __ldcg(hp + j * 32);
#pragma unroll
                for (int blk = 0; blk < 4; blk++) {
                    float2 hcur[4];
#pragma unroll
                    for (int j = 0; j < 4; j++) hcur[j] = hbuf[j];
                    if (blk < 3) {
#pragma unroll
                        for (int j = 0; j < 4; j++)
                            hbuf[j] = __ldcg(hp + ((blk + 1) * 4 + j) * 32);
                    }
#pragma unroll
                    for (int j = 0; j < 4; j++) {
                        const float4* wk = wp + (blk * 4 + j) * 136;
                        float4 w0 = wk[0], w1 = wk[1], w2 = wk[2], w3 = wk[3];
                        float2 h2 = hcur[j];
#pragma unroll
                        for (int b = 0; b < 2; b++) {
                            float hv = b ? h2.y : h2.x;
                            float2 hb = make_float2(hv, hv);
                            ffma2(acc[0][0][b], make_float2(w0.x, w0.y), hb);
                            ffma2(acc[0][1][b], make_float2(w0.z, w0.w), hb);
                            ffma2(acc[1][0][b], make_float2(w1.x, w1.y), hb);
                            ffma2(acc[1][1][b], make_float2(w1.z, w1.w), hb);
                            ffma2(acc[2][0][b], make_float2(w2.x, w2.y), hb);
                            ffma2(acc[2][1][b], make_float2(w2.z, w2.w), hb);
                            ffma2(acc[3][0][b], make_float2(w3.x, w3.y), hb);
                            ffma2(acc[3][1][b], make_float2(w3.z, w3.w), hb);
                        }
                    }
                }
            }

            // ---- reduce-scatter over kq bits ----
#pragma unroll
            for (int gp = 0; gp < 2; gp++)
#pragma unroll
                for (int dp2 = 0; dp2 < 2; dp2++)
#pragma unroll
                    for (int b = 0; b < BPL; b++) {
                        float2 X = acc[gp][dp2][b], Y = acc[2 + gp][dp2][b];
                        float gx = b2 ? X.x : Y.x, gy = b2 ? X.y : Y.y;
                        float rx = __shfl_xor_sync(0xffffffffu, gx, 4);
                        float ry = __shfl_xor_sync(0xffffffffu, gy, 4);
                        float kx = b2 ? Y.x : X.x, ky = b2 ? Y.y : X.y;
                        acc[gp][dp2][b] = make_float2(kx + rx, ky + ry);
                    }
#pragma unroll
            for (int gp = 0; gp < 2; gp++)
#pragma unroll
                for (int b = 0; b < BPL; b++) {
                    float2 X = acc[gp][0][b], Y = acc[gp][1][b];
                    float gx = b3 ? X.x : Y.x, gy = b3 ? X.y : Y.y;
                    float rx = __shfl_xor_sync(0xffffffffu, gx, 8);
                    float ry = __shfl_xor_sync(0xffffffffu, gy, 8);
                    float kx = b3 ? Y.x : X.x, ky = b3 ? Y.y : X.y;
                    acc[gp][0][b] = make_float2(kx + rx, ky + ry);
                }
            if constexpr (BTv == 16) {
#pragma unroll
                for (int gp = 0; gp < 2; gp++)
#pragma unroll
                    for (int bq = 0; bq < 2; bq++) {
                        float2 X = acc[gp][0][bq], Y = acc[gp][0][2 + bq];
                        float gx = b4 ? X.x : Y.x, gy = b4 ? X.y : Y.y;
                        float rx = __shfl_xor_sync(0xffffffffu, gx, 16);
                        float ry = __shfl_xor_sync(0xffffffffu, gy, 16);
                        float kx = b4 ? Y.x : X.x, ky = b4 ? Y.y : X.y;
                        acc[gp][0][bq] = make_float2(kx + rx, ky + ry);
                    }
                float* gb = gredb + ((rg * 4 + kh) * 16) * 20 + (8 * b2 + 2 * b3);
#pragma unroll
                for (int gp = 0; gp < 2; gp++)
#pragma unroll
                    for (int bq = 0; bq < 2; bq++) {
                        int batch = 4 * bp + 2 * b4 + bq;
                        *reinterpret_cast<float2*>(gb + batch * 20 + gp * 4)
                            = acc[gp][0][bq];
                    }
            } else {
                float2 res[2];
#pragma unroll
                for (int gp = 0; gp < 2; gp++) {
                    float2 X = acc[gp][0][0], Y = acc[gp][0][1];
                    float gx = b4 ? X.x : Y.x, gy = b4 ? X.y : Y.y;
                    float rx = __shfl_xor_sync(0xffffffffu, gx, 16);
                    float ry = __shfl_xor_sync(0xffffffffu, gy, 16);
                    float kx = b4 ? Y.x : X.x, ky = b4 ? Y.y : X.y;
                    res[gp] = make_float2(kx + rx, ky + ry);
                }
                float* gb = gredb + ((rg * 4 + kh) * 8 + (2 * bp + b4)) * 20
                            + (8 * b2 + 2 * b3);
#pragma unroll
                for (int gp = 0; gp < 2; gp++)
                    *reinterpret_cast<float2*>(gb + gp * 4) = res[gp];
            }
            // quad handoff: act warps pass only after quad's gred (and h reads) done
            asm volatile("bar.sync %0, 128;" :: "r"(rg + 1) : "memory");

            // ---- activation: act warps only; then they alone gate the step ----
            if (actw) {
                if (t < alen) {
                    constexpr int KST = BTv * 20;
                    const float* g0 = gredb + ((rg * 4 + 0) * BTv + ab) * 20;
                    const float* g1 = g0 + KST;
                    const float* g2 = g1 + KST;
                    const float* g3 = g2 + KST;
                    float gi = g0[dj] + g1[dj] + g2[dj] + g3[dj]
                             + wxb[(rg * 16 + dj) * 32 + tok];
                    float gf = g0[4 + dj] + g1[4 + dj] + g2[4 + dj] + g3[4 + dj]
                             + wxb[(rg * 16 + 4 + dj) * 32 + tok];
                    float gg = g0[8 + dj] + g1[8 + dj] + g2[8 + dj] + g3[8 + dj]
                             + wxb[(rg * 16 + 8 + dj) * 32 + tok];
                    float go = g0[12 + dj] + g1[12 + dj] + g2[12 + dj] + g3[12 + dj]
                             + wxb[(rg * 16 + 12 + dj) * 32 + tok];
                    float cn = sigm(gf) * creg + sigm(gi) * tanha(gg);
                    creg = cn;
                    __stcg(hw + dG * BTv + ab, sigm(go) * tanha(cn));
                } else if (t == alen) {
                    __stcg(hw + dG * BTv + ab, __ldcg(hr + dG * BTv + ab));
                }
                // act-warp barrier (covers all quads), then single release-add
                asm volatile("bar.sync 5, %0;" :: "n"(NACT * 32) : "memory");
                if (w == 0 && lane == 0) rel_add(cnt);
            }
        }
    } else {
        // ---- BTv == 32 (all warps are act warps): R14 structure ----
        const int rg = w >> 1, kh = w & 1;
        const int kbase = kh * 256 + kq;
        const int rg4 = rg >> 1, off = 2 * (rg & 1);
        const int sb = B0 + lane;
        const int alen = slen[sb];
        const int dG = d0 + 2 * rg + kh;
        const int* tokrow = tokens + sorder[sb] * SS;
        float creg = 0.f;

        for (int t = 0; t < ctalen; t++) {
            acq_poll(cnt, (unsigned)(t + 1) * NGC);
            const float* hr = (t & 1) ? hq1 : hq0;
            float*       hw = (t & 1) ? hq0 : hq1;
            int tok = 0;
            if (t < alen) tok = __ldg(tokrow + t);

            const float4* hp = reinterpret_cast<const float4*>(hr) + kbase * 8 + 2 * bp;
            const float* wbase = wsp + kbase * 68 + rg4 * 16 + off;
            float2 acc[4][8];
#pragma unroll
            for (int gg = 0; gg < 4; gg++)
#pragma unroll
                for (int b = 0; b < 8; b++) acc[gg][b] = make_float2(0.f, 0.f);

            float4 hbuf[8];
#pragma unroll
            for (int j = 0; j < 4; j++) {
                hbuf[2 * j]     = __ldcg(hp + j * 64);
                hbuf[2 * j + 1] = __ldcg(hp + j * 64 + 1);
            }
#pragma unroll 2
            for (int blk = 0; blk < 8; blk++) {
                float4 hcur[8];
#pragma unroll
                for (int j = 0; j < 8; j++) hcur[j] = hbuf[j];
                if (blk < 7) {
#pragma unroll
                    for (int j = 0; j < 4; j++) {
                        hbuf[2 * j]     = __ldcg(hp + ((blk + 1) * 4 + j) * 64);
                        hbuf[2 * j + 1] = __ldcg(hp + ((blk + 1) * 4 + j) * 64 + 1);
                    }
                }
#pragma unroll
                for (int j = 0; j < 4; j++) {
                    const float* wk = wbase + (blk * 4 + j) * 544;
                    float2 wg0 = *reinterpret_cast<const float2*>(wk);
                    float2 wg1 = *reinterpret_cast<const float2*>(wk + 4);
                    float2 wg2 = *reinterpret_cast<const float2*>(wk + 8);
                    float2 wg3 = *reinterpret_cast<const float2*>(wk + 12);
                    float4 hA = hcur[2 * j], hB = hcur[2 * j + 1];
#pragma unroll
                    for (int b = 0; b < 8; b++) {
                        float hv = (b == 0) ? hA.x : (b == 1) ? hA.y
                                 : (b == 2) ? hA.z : (b == 3) ? hA.w
                                 : (b == 4) ? hB.x : (b == 5) ? hB.y
                                 : (b == 6) ? hB.z : hB.w;
                        float2 hb = make_float2(hv, hv);
                        ffma2(acc[0][b], wg0, hb);
                        ffma2(acc[1][b], wg1, hb);
                        ffma2(acc[2][b], wg2, hb);
                        ffma2(acc[3][b], wg3, hb);
                    }
                }
            }

#pragma unroll
            for (int gp = 0; gp < 2; gp++)
#pragma unroll
                for (int b = 0; b < 8; b++) {
                    float2 X = acc[gp][b], Y = acc[2 + gp][b];
                    float gx = b2 ? X.x : Y.x, gy = b2 ? X.y : Y.y;
                    float rx = __shfl_xor_sync(0xffffffffu, gx, 4);
                    float ry = __shfl_xor_sync(0xffffffffu, gy, 4);
                    float kx = b2 ? Y.x : X.x, ky = b2 ? Y.y : X.y;
                    acc[gp][b] = make_float2(kx + rx, ky + ry);
                }
#pragma unroll
            for (int b = 0; b < 8; b++) {
                float2 X = acc[0][b], Y = acc[1][b];
                float gx = b3 ? X.x : Y.x, gy = b3 ? X.y : Y.y;
                float rx = __shfl_xor_sync(0xffffffffu, gx, 8);
                float ry = __shfl_xor_sync(0xffffffffu, gy, 8);
                float kx = b3 ? Y.x : X.x, ky = b3 ? Y.y : X.y;
                acc[0][b] = make_float2(kx + rx, ky + ry);
            }
            float2 r4[4];
#pragma unroll
            for (int j = 0; j < 4; j++) {
                float2 X = acc[0][j], Y = acc[0][4 + j];
                float gx = b4 ? X.x : Y.x, gy = b4 ? X.y : Y.y;
                float rx = __shfl_xor_sync(0xffffffffu, gx, 16);
                float ry = __shfl_xor_sync(0xffffffffu, gy, 16);
                float kx = b4 ? Y.x : X.x, ky = b4 ? Y.y : X.y;
                r4[j] = make_float2(kx + rx, ky + ry);
            }
            {
                float* gb = gred + ((rg * 2 + kh) * 32) * 10 + (2 * b2 + b3) * 2;
#pragma unroll
                for (int j = 0; j < 4; j++)
                    *reinterpret_cast<float2*>(gb + (8 * bp + 4 * b4 + j) * 10) = r4[j];
            }
            asm volatile("bar.sync %0, 64;" :: "r"(rg + 1) : "memory");

            if (t < alen) {
                const float* p0 = gred + ((rg * 2 + 0) * 32 + lane) * 10 + kh;
                const float* p1 = gred + ((rg * 2 + 1) * 32 + lane) * 10 + kh;
                int dj = off + kh;
                float gi = p0[0] + p1[0] + wxb[(rg4 * 16 + dj) * 32 + tok];
                float gf = p0[2] + p1[2] + wxb[(rg4 * 16 + 4 + dj) * 32 + tok];
                float gg = p0[4] + p1[4] + wxb[(rg4 * 16 + 8 + dj) * 32 + tok];
                float go = p0[6] + p1[6] + wxb[(rg4 * 16 + 12 + dj) * 32 + tok];
                float cn = sigm(gf) * creg + sigm(gi) * tanha(gg);
                creg = cn;
                __stcg(hw + dG * 32 + lane, sigm(go) * tanha(cn));
            } else if (t == alen) {
                __stcg(hw + dG * 32 + lane, __ldcg(hr + dG * 32 + lane));
            }
            grp_arrive(tid, cnt);
        }
    }
}

// ---------------------------------------------------------------------------
__global__ void __launch_bounds__(THREADS, 1) lstm_persistent_kernel(
    const int* __restrict__ tokens, const int* __restrict__ lengths,
    const float* __restrict__ W_ih, const float* __restrict__ W_hh,
    const float* __restrict__ b_ih, const float* __restrict__ b_hh,
    const float* __restrict__ fc_w, const float* __restrict__ fc_b,
    float* __restrict__ out)
{
    extern __shared__ char smem_raw[];
    float* wsp  = reinterpret_cast<float*>(smem_raw);
    float* wxb  = wsp + WSP_FLOATS;
    float* gred = wxb + WXB_FLOATS;
    int*   slen   = reinterpret_cast<int*>(gred + GRD_FLOATS);
    int*   sorder = slen + BB;
    int*   lens   = sorder + BB;

    const int tid = threadIdx.x;
    const int g  = blockIdx.x >> 5;          // group 0..3
    const int dt = blockIdx.x & 31;          // dim tile 0..31
    const int d0 = dt * 16;
    const int B0g = (g == 0) ? 0 : (g == 1) ? 8 : (g == 2) ? 16 : 32;
    const int BTg = (g <= 1) ? 8 : (g == 2) ? 16 : 32;
    unsigned* cnt = &g_cnt[g * 32];
    float* hq0 = g_h[0] + B0g * HH;
    float* hq1 = g_h[1] + B0g * HH;

    for (int idx = tid; idx < 64 * HH; idx += THREADS) {
        int r = idx >> 9, k = idx & (HH - 1);
        int rg4 = r >> 4, gate = (r >> 2) & 3, dj = r & 3;
        wsp[k * 68 + r] = W_hh[(gate * HH + d0 + rg4 * 4 + dj) * HH + k];
    }
    for (int idx = tid; idx < 64 * VV; idx += THREADS) {
        int r = idx / VV, v = idx - r * VV;
        int rg4 = r >> 4, gate = (r >> 2) & 3, dj = r & 3;
        int R = gate * HH + d0 + rg4 * 4 + dj;
        wxb[r * 32 + v] = W_ih[R * VV + v] + b_ih[R] + b_hh[R];
    }
    if (tid < BB) lens[tid] = lengths[tid];
    __syncthreads();
    if (tid < BB) {
        int L = lens[tid], rk = 0;
        for (int b2 = 0; b2 < BB; b2++) {
            int L2 = lens[b2];
            rk += (L2 > L) || (L2 == L && b2 < tid);
        }
        sorder[rk] = tid;
        slen[rk]   = L;
    }
    if (tid < 16 * BTg) {
        int d = tid / BTg, b = tid - d * BTg;
        hq0[(d0 + d) * BTg + b] = 0.f;
    }

    grp_arrive(tid, cnt);          // init: __syncthreads + tid0 release

    if (g <= 1)      run_lstm<8>(tokens, wsp, wxb, gred, slen, sorder,
                                 hq0, hq1, cnt, B0g, d0, tid);
    else if (g == 2) run_lstm<16>(tokens, wsp, wxb, gred, slen, sorder,
                                  hq0, hq1, cnt, B0g, d0, tid);
    else             run_lstm<32>(tokens, wsp, wxb, gred, slen, sorder,
                                  hq0, hq1, cnt, B0g, d0, tid);

    // ---- final FC for this group (dt==0 CTA) ----
    if (dt == 0) {
        const int ctalen = slen[B0g];
        acq_poll(cnt, (unsigned)(ctalen + 1) * NGC);   // final h visible
        const float* hf = ((ctalen & 1) ? g_h[1] : g_h[0]) + B0g * HH;
        int bi = tid >> 4, kp = tid & 15;
        if (bi < BTg) {
            float p = 0.f;
#pragma unroll 8
            for (int i = 0; i < 32; i++) {
                int k = kp * 32 + i;
                p += __ldcg(hf + k * BTg + bi) * __ldg(fc_w + k);
            }
            p += __shfl_xor_sync(0xffffffffu, p, 8);
            p += __shfl_xor_sync(0xffffffffu, p, 4);
            p += __shfl_xor_sync(0xffffffffu, p, 2);
            p += __shfl_xor_sync(0xffffffffu, p, 1);
            if (kp == 0) out[B0g + bi] = p + __ldg(fc_b);
        }
    }
}

extern "C" void kernel_launch(void* const* d_in, const int* in_sizes, int n_in,
                              void* d_out, int out_size) {
    const int*   tokens  = (const int*)d_in[0];
    const int*   lengths = (const int*)d_in[1];
    const float* W_ih    = (const float*)d_in[2];
    const float* W_hh    = (const float*)d_in[3];
    const float* b_ih    = (const float*)d_in[4];
    const float* b_hh    = (const float*)d_in[5];
    const float* fc_w    = (const float*)d_in[6];
    const float* fc_b    = (const float*)d_in[7];
    float* out = (float*)d_out;

    cudaFuncSetAttribute(lstm_persistent_kernel,
                         cudaFuncAttributeMaxDynamicSharedMemorySize, SMEM_BYTES);
    init_barrier_kernel<<<1, 1>>>();
    lstm_persistent_kernel<<<128, THREADS, SMEM_BYTES>>>(
        tokens, lengths, W_ih, W_hh, b_ih, b_hh, fc_w, fc_b, out);
}